// round 7
// baseline (speedup 1.0000x reference)
#include <cuda_runtime.h>
#include <cuda_bf16.h>
#include <cstdint>

#define NN 50000
#define NE 800000
#define NM (NE + NN)
#define HD 256
#define EPSV 1e-5f

// ==================== PTX helpers (sm_80-era, compile for plain sm_103) ====
#define LDSM4(r, addr) asm volatile( \
    "ldmatrix.sync.aligned.m8n8.x4.shared.b16 {%0,%1,%2,%3}, [%4];" \
    : "=r"((r)[0]), "=r"((r)[1]), "=r"((r)[2]), "=r"((r)[3]) : "r"(addr))

#define MMA_BF16(d, a, b0, b1) asm volatile( \
    "mma.sync.aligned.m16n8k16.row.col.f32.bf16.bf16.f32 " \
    "{%0,%1,%2,%3}, {%4,%5,%6,%7}, {%8,%9}, {%0,%1,%2,%3};" \
    : "+f"((d)[0]), "+f"((d)[1]), "+f"((d)[2]), "+f"((d)[3]) \
    : "r"((a)[0]), "r"((a)[1]), "r"((a)[2]), "r"((a)[3]), "r"(b0), "r"(b1))

#define CP_ASYNC16(dst, src) \
    asm volatile("cp.async.cg.shared.global [%0], [%1], 16;" :: "r"(dst), "l"(src))
#define CP_COMMIT() asm volatile("cp.async.commit_group;" ::: "memory")
#define CP_WAIT0() asm volatile("cp.async.wait_group 0;" ::: "memory")

__device__ __forceinline__ uint32_t smem_to_u32(const void* smem_ptr) {
    uint32_t addr;
    asm("{ .reg .u64 tmp; cvta.to.shared.u64 tmp, %1; cvt.u32.u64 %0, tmp; }"
        : "=r"(addr) : "l"(smem_ptr));
    return addr;
}

// ==================== device scratch ====================
__device__ __align__(256) float g_xw[(size_t)NN * HD];
__device__ __align__(256) __nv_bfloat16 g_ah[(size_t)NN * HD];
__device__ __align__(256) __nv_bfloat16 g_al[(size_t)NN * HD];
__device__ __align__(256) __nv_bfloat16 g_w1t_h[256 * 128], g_w1t_l[256 * 128];
__device__ __align__(256) __nv_bfloat16 g_w2t_h[256 * 256], g_w2t_l[256 * 256];
__device__ __align__(256) __nv_bfloat16 g_w3t_h[256 * 256], g_w3t_l[256 * 256];
__device__ __align__(256) __nv_bfloat16 g_wf1t_h[128 * 256], g_wf1t_l[128 * 256];
__device__ int   g_cnt[NN];
__device__ int   g_off[NN + 1];
__device__ int   g_cur[NN];
__device__ int   g_src[NM];
__device__ float g_nrm[NM];
__device__ int   g_is64;

__device__ __forceinline__ int edge_val(const void* ei, int which, int e) {
    if (g_is64) return (int)((const long long*)ei)[(size_t)which * NE + e];
    return ((const int*)ei)[(size_t)which * NE + e];
}

// ======= fused: warp-parallel edge dtype detect + cnt/cur init =======
__global__ void k_detinit(const int* __restrict__ p) {
    int i = blockIdx.x * blockDim.x + threadIdx.x;
    if (blockIdx.x == 0 && threadIdx.x < 32) {
        int lane = threadIdx.x;
        int nz = 0;
        for (int j = lane; j < 1024; j += 32) nz |= p[2 * j + 1];
        unsigned any = __ballot_sync(0xffffffffu, nz != 0);
        if (lane == 0) g_is64 = (any == 0) ? 1 : 0;
    }
    if (i < NN) { g_cnt[i] = 1; g_cur[i] = 1; }
}

__global__ void k_deg(const void* __restrict__ ei) {
    int e = blockIdx.x * blockDim.x + threadIdx.x;
    if (e < NE) atomicAdd(&g_cnt[edge_val(ei, 1, e)], 1);
}

// single-block exclusive scan over g_cnt -> g_off
__global__ void k_scan() {
    __shared__ int s[1024];
    const int CH = (NN + 1023) / 1024;
    int tid = threadIdx.x;
    int base = tid * CH;
    int sum = 0;
    for (int i = 0; i < CH; i++) { int idx = base + i; if (idx < NN) sum += g_cnt[idx]; }
    s[tid] = sum;
    __syncthreads();
    for (int o = 1; o < 1024; o <<= 1) {
        int v = (tid >= o) ? s[tid - o] : 0;
        __syncthreads();
        s[tid] += v;
        __syncthreads();
    }
    int run = (tid == 0) ? 0 : s[tid - 1];
    for (int i = 0; i < CH; i++) {
        int idx = base + i;
        if (idx < NN) { g_off[idx] = run; run += g_cnt[idx]; }
    }
    if (tid == 1023) g_off[NN] = s[1023];
}

// ============ fused: self-loops + edge fill ============
__global__ void k_fillself(const void* __restrict__ ei) {
    int t = blockIdx.x * blockDim.x + threadIdx.x;
    if (t < NN) {
        int o = g_off[t];
        g_src[o] = t;
        g_nrm[o] = 1.0f / (float)g_cnt[t];
    } else if (t < NN + NE) {
        int e = t - NN;
        int r = edge_val(ei, 0, e);
        int c = edge_val(ei, 1, e);
        int p = atomicAdd(&g_cur[c], 1);
        int s = g_off[c] + p;
        g_src[s] = r;
        g_nrm[s] = rsqrtf((float)g_cnt[r]) * rsqrtf((float)g_cnt[c]);
    }
}

// ====== fused weight transpose + bf16 split for all 4 weight matrices ======
__global__ void k_wtall(
    const float* __restrict__ W1, const float* __restrict__ W2,
    const float* __restrict__ W3, const float* __restrict__ Wf1,
    __nv_bfloat16* __restrict__ w1h, __nv_bfloat16* __restrict__ w1l,
    __nv_bfloat16* __restrict__ w2h, __nv_bfloat16* __restrict__ w2l,
    __nv_bfloat16* __restrict__ w3h, __nv_bfloat16* __restrict__ w3l,
    __nv_bfloat16* __restrict__ wfh, __nv_bfloat16* __restrict__ wfl)
{
    int idx = blockIdx.x * blockDim.x + threadIdx.x;
    const float* W; __nv_bfloat16 *Th, *Tl; int K, Nc, local;
    if (idx < 32768)       { W = W1;  Th = w1h; Tl = w1l; K = 128; Nc = 256; local = idx; }
    else if (idx < 98304)  { W = W2;  Th = w2h; Tl = w2l; K = 256; Nc = 256; local = idx - 32768; }
    else if (idx < 163840) { W = W3;  Th = w3h; Tl = w3l; K = 256; Nc = 256; local = idx - 98304; }
    else if (idx < 196608) { W = Wf1; Th = wfh; Tl = wfl; K = 256; Nc = 128; local = idx - 163840; }
    else return;
    int k = local / Nc, n = local % Nc;
    float a = W[local];
    __nv_bfloat16 hi = __float2bfloat16_rn(a);
    __nv_bfloat16 lo = __float2bfloat16_rn(a - __bfloat162float(hi));
    Th[(size_t)n * K + k] = hi;
    Tl[(size_t)n * K + k] = lo;
}

// ==================== x -> bf16 hi/lo ====================
__global__ void k_xcvt(const float* __restrict__ x, __nv_bfloat16* __restrict__ Ah,
                       __nv_bfloat16* __restrict__ Al, int total) {
    int idx = blockIdx.x * blockDim.x + threadIdx.x;
    if (idx >= total) return;
    float a = x[idx];
    __nv_bfloat16 hi = __float2bfloat16_rn(a);
    Ah[idx] = hi;
    Al[idx] = __float2bfloat16_rn(a - __bfloat162float(hi));
}

// ============ bf16x3 GEMM, 64x64 warp tile (48 FLOP/smem-byte) ============
// C[M,256] = A[M,K] @ W[K,256].  CTA tile 128(M) x 256(N), 8 warps as 2m x 4n,
// warp tile 64x64.  BK=32 double-buffered cp.async, 1 CTA/SM (reg-heavy).
template<int K>
__global__ __launch_bounds__(256, 1) void k_mma2(
    const __nv_bfloat16* __restrict__ Ah, const __nv_bfloat16* __restrict__ Al,
    const __nv_bfloat16* __restrict__ Bh, const __nv_bfloat16* __restrict__ Bl,
    float* __restrict__ C, int M)
{
    constexpr int BK = 32;
    constexpr int NC_CHUNK = K / BK;
    constexpr int SA = BK + 8;                   // 40 bf16 = 80B row stride
    constexpr int QTRA = 128 * SA * 2;           // 10240 B per A half
    constexpr int QTRB = 256 * SA * 2;           // 20480 B per B half
    constexpr int STAGE = 2 * QTRA + 2 * QTRB;   // 61440 B

    extern __shared__ char smem[];
    uint32_t smem_base = smem_to_u32(smem);
    int tid = threadIdx.x;
    int lane = tid & 31;
    int wid = tid >> 5;
    int bm = blockIdx.x * 128;
    int wm = (wid & 1) * 64;
    int wn = (wid >> 1) * 64;
    int lt = lane >> 3;
    int lr = lane & 7;

    uint32_t a_base[4][2];
#pragma unroll
    for (int mi = 0; mi < 4; mi++)
#pragma unroll
        for (int w = 0; w < 2; w++)
            a_base[mi][w] = smem_base + w * QTRA +
                ((wm + mi * 16 + (lt & 1) * 8 + lr) * SA + (lt >> 1) * 8) * 2;
    uint32_t b_base[4][2];
#pragma unroll
    for (int nj = 0; nj < 4; nj++)
#pragma unroll
        for (int w = 0; w < 2; w++)
            b_base[nj][w] = smem_base + 2 * QTRA + w * QTRB +
                ((wn + nj * 16 + (lt >> 1) * 8 + lr) * SA + (lt & 1) * 8) * 2;

    auto issue_chunk = [&](int c, int buf) {
        uint32_t dst = smem_base + buf * STAGE;
#pragma unroll
        for (int t = 0; t < 12; t++) {
            int i = tid + t * 256;               // 0..3071 uint4 slots
            if (i < 1024) {                      // A: [hi(512)|lo(512)]
                int w = i >> 9;
                int rem = i & 511;
                int m = rem >> 2;
                int k = (rem & 3) * 8;
                int gm = bm + m;
                if (gm > M - 1) gm = M - 1;      // clamp: safe reads, never stored
                const __nv_bfloat16* src = (w ? Al : Ah) + (size_t)gm * K + c * BK + k;
                CP_ASYNC16(dst + w * QTRA + (m * SA + k) * 2, src);
            } else {                             // B: [hi(1024)|lo(1024)]
                int j = i - 1024;
                int w = j >> 10;
                int rem = j & 1023;
                int n = rem >> 2;
                int k = (rem & 3) * 8;
                const __nv_bfloat16* src = (w ? Bl : Bh) + (size_t)n * K + c * BK + k;
                CP_ASYNC16(dst + 2 * QTRA + w * QTRB + (n * SA + k) * 2, src);
            }
        }
    };

    float acc[4][8][4];
#pragma unroll
    for (int mi = 0; mi < 4; mi++)
#pragma unroll
        for (int ni = 0; ni < 8; ni++)
#pragma unroll
            for (int v = 0; v < 4; v++) acc[mi][ni][v] = 0.f;

    issue_chunk(0, 0);
    CP_COMMIT();

    for (int c = 0; c < NC_CHUNK; c++) {
        CP_WAIT0();
        __syncthreads();
        if (c + 1 < NC_CHUNK) { issue_chunk(c + 1, (c + 1) & 1); CP_COMMIT(); }

        uint32_t sbuf = (uint32_t)(c & 1) * STAGE;
#pragma unroll
        for (int ks = 0; ks < BK / 16; ks++) {
            uint32_t o = sbuf + ks * 32;
            uint32_t ahf[4][4], alf[4][4];
#pragma unroll
            for (int mi = 0; mi < 4; mi++) {
                LDSM4(ahf[mi], a_base[mi][0] + o);
                LDSM4(alf[mi], a_base[mi][1] + o);
            }
            uint32_t bhB[2][4], blB[2][4];
            LDSM4(bhB[0], b_base[0][0] + o);
            LDSM4(blB[0], b_base[0][1] + o);
#pragma unroll
            for (int nj = 0; nj < 4; nj++) {
                int cur = nj & 1, nxt = cur ^ 1;
                if (nj < 3) {
                    LDSM4(bhB[nxt], b_base[nj + 1][0] + o);
                    LDSM4(blB[nxt], b_base[nj + 1][1] + o);
                }
                // hh term (8 MMAs), hl term (8), lh term (8): same-acc gap = 8
#pragma unroll
                for (int mi = 0; mi < 4; mi++)
                    MMA_BF16(acc[mi][2 * nj],     ahf[mi], bhB[cur][0], bhB[cur][1]);
#pragma unroll
                for (int mi = 0; mi < 4; mi++)
                    MMA_BF16(acc[mi][2 * nj + 1], ahf[mi], bhB[cur][2], bhB[cur][3]);
#pragma unroll
                for (int mi = 0; mi < 4; mi++)
                    MMA_BF16(acc[mi][2 * nj],     ahf[mi], blB[cur][0], blB[cur][1]);
#pragma unroll
                for (int mi = 0; mi < 4; mi++)
                    MMA_BF16(acc[mi][2 * nj + 1], ahf[mi], blB[cur][2], blB[cur][3]);
#pragma unroll
                for (int mi = 0; mi < 4; mi++)
                    MMA_BF16(acc[mi][2 * nj],     alf[mi], bhB[cur][0], bhB[cur][1]);
#pragma unroll
                for (int mi = 0; mi < 4; mi++)
                    MMA_BF16(acc[mi][2 * nj + 1], alf[mi], bhB[cur][2], bhB[cur][3]);
            }
        }
    }

    // ---- epilogue: fp32 store to C (row stride 256) ----
    int g = lane >> 2, tg = lane & 3;
#pragma unroll
    for (int mi = 0; mi < 4; mi++) {
        int r0 = bm + wm + mi * 16 + g;
#pragma unroll
        for (int ni = 0; ni < 8; ni++) {
            int col = wn + ni * 8 + tg * 2;
            float2 v0 = make_float2(acc[mi][ni][0], acc[mi][ni][1]);
            float2 v1 = make_float2(acc[mi][ni][2], acc[mi][ni][3]);
            if (r0 < M)     *(float2*)(C + (size_t)r0 * 256 + col) = v0;
            if (r0 + 8 < M) *(float2*)(C + (size_t)(r0 + 8) * 256 + col) = v1;
        }
    }
}

// ======== head GEMM (32x64 warp tile) with fused relu+Wf2 reduction ========
// out[m] = sum_col relu( (A@Wf1)[m,col] + bf1[col] ) * Wf2[col] + bf2
__global__ __launch_bounds__(256, 2) void k_head(
    const __nv_bfloat16* __restrict__ Ah, const __nv_bfloat16* __restrict__ Al,
    const __nv_bfloat16* __restrict__ Bh, const __nv_bfloat16* __restrict__ Bl,
    const float* __restrict__ bias, int M,
    const float* __restrict__ wf2, const float* __restrict__ bf2,
    float* __restrict__ outp)
{
    constexpr int K = 256;
    constexpr int BK = 32;
    constexpr int NC_CHUNK = K / BK;
    constexpr int SA = BK + 8;
    constexpr int QTR = 128 * SA * 2;
    constexpr int STAGE = 4 * QTR;

    extern __shared__ char smem[];
    __shared__ float red[128];
    uint32_t smem_base = smem_to_u32(smem);
    int tid = threadIdx.x;
    int lane = tid & 31;
    int wid = tid >> 5;
    int bm = blockIdx.x * 128;
    int wm = (wid >> 1) * 32;
    int wn = (wid & 1) * 64;
    int lt = lane >> 3;
    int lr = lane & 7;

    if (tid < 128) red[tid] = 0.f;

    uint32_t a_base[2][2];
#pragma unroll
    for (int mi = 0; mi < 2; mi++)
#pragma unroll
        for (int w = 0; w < 2; w++)
            a_base[mi][w] = smem_base + w * QTR +
                ((wm + mi * 16 + (lt & 1) * 8 + lr) * SA + (lt >> 1) * 8) * 2;
    uint32_t b_base[4][2];
#pragma unroll
    for (int nj = 0; nj < 4; nj++)
#pragma unroll
        for (int w = 0; w < 2; w++)
            b_base[nj][w] = smem_base + 2 * QTR + w * QTR +
                ((wn + nj * 16 + (lt >> 1) * 8 + lr) * SA + (lt & 1) * 8) * 2;

    auto issue_chunk = [&](int c, int buf) {
        uint32_t dstbase = smem_base + buf * STAGE;
#pragma unroll
        for (int t = 0; t < 8; t++) {
            int i = tid + t * 256;
            int which = i >> 9;
            int rem = i & 511;
            int m = rem >> 2;
            int k = (rem & 3) * 8;
            const __nv_bfloat16* src;
            if (which < 2) {
                int gm = bm + m;
                if (gm > M - 1) gm = M - 1;
                src = (which ? Al : Ah) + (size_t)gm * K + c * BK + k;
            } else {
                src = (which == 2 ? Bh : Bl) + (size_t)(m)*K + c * BK + k;  // Nc=128, bn=0
            }
            CP_ASYNC16(dstbase + which * QTR + (m * SA + k) * 2, src);
        }
    };

    float acc[2][8][4];
#pragma unroll
    for (int mi = 0; mi < 2; mi++)
#pragma unroll
        for (int ni = 0; ni < 8; ni++)
#pragma unroll
            for (int v = 0; v < 4; v++) acc[mi][ni][v] = 0.f;

    issue_chunk(0, 0);
    CP_COMMIT();

    for (int c = 0; c < NC_CHUNK; c++) {
        CP_WAIT0();
        __syncthreads();
        if (c + 1 < NC_CHUNK) { issue_chunk(c + 1, (c + 1) & 1); CP_COMMIT(); }

        uint32_t sbuf = (uint32_t)(c & 1) * STAGE;
#pragma unroll
        for (int ks = 0; ks < BK / 16; ks++) {
            uint32_t o = sbuf + ks * 32;
            uint32_t ah[2][4], al[2][4];
            LDSM4(ah[0], a_base[0][0] + o);
            LDSM4(ah[1], a_base[1][0] + o);
            LDSM4(al[0], a_base[0][1] + o);
            LDSM4(al[1], a_base[1][1] + o);
            uint32_t bhB[2][4], blB[2][4];
            LDSM4(bhB[0], b_base[0][0] + o);
            LDSM4(blB[0], b_base[0][1] + o);
#pragma unroll
            for (int nj = 0; nj < 4; nj++) {
                int cur = nj & 1, nxt = cur ^ 1;
                if (nj < 3) {
                    LDSM4(bhB[nxt], b_base[nj + 1][0] + o);
                    LDSM4(blB[nxt], b_base[nj + 1][1] + o);
                }
                MMA_BF16(acc[0][2 * nj],     ah[0], bhB[cur][0], bhB[cur][1]);
                MMA_BF16(acc[1][2 * nj],     ah[1], bhB[cur][0], bhB[cur][1]);
                MMA_BF16(acc[0][2 * nj + 1], ah[0], bhB[cur][2], bhB[cur][3]);
                MMA_BF16(acc[1][2 * nj + 1], ah[1], bhB[cur][2], bhB[cur][3]);
                MMA_BF16(acc[0][2 * nj],     ah[0], blB[cur][0], blB[cur][1]);
                MMA_BF16(acc[1][2 * nj],     ah[1], blB[cur][0], blB[cur][1]);
                MMA_BF16(acc[0][2 * nj + 1], ah[0], blB[cur][2], blB[cur][3]);
                MMA_BF16(acc[1][2 * nj + 1], ah[1], blB[cur][2], blB[cur][3]);
                MMA_BF16(acc[0][2 * nj],     al[0], bhB[cur][0], bhB[cur][1]);
                MMA_BF16(acc[1][2 * nj],     al[1], bhB[cur][0], bhB[cur][1]);
                MMA_BF16(acc[0][2 * nj + 1], al[0], bhB[cur][2], bhB[cur][3]);
                MMA_BF16(acc[1][2 * nj + 1], al[1], bhB[cur][2], bhB[cur][3]);
            }
        }
    }

    int g = lane >> 2, tg = lane & 3;
    __syncthreads();
#pragma unroll
    for (int mi = 0; mi < 2; mi++) {
        float p0 = 0.f, p1 = 0.f;
#pragma unroll
        for (int ni = 0; ni < 8; ni++) {
            int col = wn + ni * 8 + tg * 2;
            float bx = bias[col], by = bias[col + 1];
            float w0 = wf2[col], w1 = wf2[col + 1];
            p0 += fmaxf(acc[mi][ni][0] + bx, 0.f) * w0
                + fmaxf(acc[mi][ni][1] + by, 0.f) * w1;
            p1 += fmaxf(acc[mi][ni][2] + bx, 0.f) * w0
                + fmaxf(acc[mi][ni][3] + by, 0.f) * w1;
        }
        atomicAdd(&red[wm + mi * 16 + g], p0);
        atomicAdd(&red[wm + mi * 16 + 8 + g], p1);
    }
    __syncthreads();
    if (tid < 128) {
        int r = bm + tid;
        if (r < M) outp[r] = red[tid] + bf2[0];
    }
}

// ======== fused aggregate(+bias)+LN+ReLU+residual -> bf16 hi/lo only ========
template<int MODE>
__global__ __launch_bounds__(256) void k_agg(
    const float* __restrict__ xw, const float* __restrict__ bias,
    const float* __restrict__ gam, const float* __restrict__ bet,
    const __nv_bfloat16* __restrict__ ph, const __nv_bfloat16* __restrict__ pl,
    __nv_bfloat16* __restrict__ oh, __nv_bfloat16* __restrict__ ol)
{
    int n = (blockIdx.x * blockDim.x + threadIdx.x) >> 5;
    int lane = threadIdx.x & 31;
    if (n >= NN) return;
    int s0 = g_off[n], s1 = g_off[n + 1];
    float4 a0 = make_float4(0.f, 0.f, 0.f, 0.f);
    float4 a1 = make_float4(0.f, 0.f, 0.f, 0.f);
    int s = s0;
    for (; s + 3 < s1; s += 4) {
        int i0 = g_src[s], i1 = g_src[s + 1], i2 = g_src[s + 2], i3 = g_src[s + 3];
        float w0 = g_nrm[s], w1 = g_nrm[s + 1], w2 = g_nrm[s + 2], w3 = g_nrm[s + 3];
        const float4* p0 = (const float4*)(xw + (size_t)i0 * HD) + (lane << 1);
        const float4* p1 = (const float4*)(xw + (size_t)i1 * HD) + (lane << 1);
        const float4* p2 = (const float4*)(xw + (size_t)i2 * HD) + (lane << 1);
        const float4* p3 = (const float4*)(xw + (size_t)i3 * HD) + (lane << 1);
        float4 u0 = p0[0], u1 = p0[1];
        float4 v0 = p1[0], v1 = p1[1];
        float4 q0 = p2[0], q1 = p2[1];
        float4 t0 = p3[0], t1 = p3[1];
        a0.x += w0 * u0.x; a0.y += w0 * u0.y; a0.z += w0 * u0.z; a0.w += w0 * u0.w;
        a1.x += w0 * u1.x; a1.y += w0 * u1.y; a1.z += w0 * u1.z; a1.w += w0 * u1.w;
        a0.x += w1 * v0.x; a0.y += w1 * v0.y; a0.z += w1 * v0.z; a0.w += w1 * v0.w;
        a1.x += w1 * v1.x; a1.y += w1 * v1.y; a1.z += w1 * v1.z; a1.w += w1 * v1.w;
        a0.x += w2 * q0.x; a0.y += w2 * q0.y; a0.z += w2 * q0.z; a0.w += w2 * q0.w;
        a1.x += w2 * q1.x; a1.y += w2 * q1.y; a1.z += w2 * q1.z; a1.w += w2 * q1.w;
        a0.x += w3 * t0.x; a0.y += w3 * t0.y; a0.z += w3 * t0.z; a0.w += w3 * t0.w;
        a1.x += w3 * t1.x; a1.y += w3 * t1.y; a1.z += w3 * t1.z; a1.w += w3 * t1.w;
    }
    for (; s < s1; s++) {
        int src = g_src[s];
        float w = g_nrm[s];
        const float4* p = (const float4*)(xw + (size_t)src * HD) + (lane << 1);
        float4 v0 = p[0], v1 = p[1];
        a0.x += w * v0.x; a0.y += w * v0.y; a0.z += w * v0.z; a0.w += w * v0.w;
        a1.x += w * v1.x; a1.y += w * v1.y; a1.z += w * v1.z; a1.w += w * v1.w;
    }
    const float4* bp = (const float4*)bias + (lane << 1);
    float4 b0 = bp[0], b1 = bp[1];
    a0.x += b0.x; a0.y += b0.y; a0.z += b0.z; a0.w += b0.w;
    a1.x += b1.x; a1.y += b1.y; a1.z += b1.z; a1.w += b1.w;

    float sm = a0.x + a0.y + a0.z + a0.w + a1.x + a1.y + a1.z + a1.w;
    float sq = a0.x * a0.x + a0.y * a0.y + a0.z * a0.z + a0.w * a0.w
             + a1.x * a1.x + a1.y * a1.y + a1.z * a1.z + a1.w * a1.w;
#pragma unroll
    for (int o = 16; o > 0; o >>= 1) {
        sm += __shfl_xor_sync(0xffffffffu, sm, o);
        sq += __shfl_xor_sync(0xffffffffu, sq, o);
    }
    float mu = sm * (1.f / HD);
    float inv = rsqrtf(sq * (1.f / HD) - mu * mu + EPSV);

    const float4* gp = (const float4*)gam + (lane << 1);
    const float4* ep = (const float4*)bet + (lane << 1);
    float4 gg0 = gp[0], gg1 = gp[1], ee0 = ep[0], ee1 = ep[1];
    float r[8];
    r[0] = fmaxf((a0.x - mu) * inv * gg0.x + ee0.x, 0.f);
    r[1] = fmaxf((a0.y - mu) * inv * gg0.y + ee0.y, 0.f);
    r[2] = fmaxf((a0.z - mu) * inv * gg0.z + ee0.z, 0.f);
    r[3] = fmaxf((a0.w - mu) * inv * gg0.w + ee0.w, 0.f);
    r[4] = fmaxf((a1.x - mu) * inv * gg1.x + ee1.x, 0.f);
    r[5] = fmaxf((a1.y - mu) * inv * gg1.y + ee1.y, 0.f);
    r[6] = fmaxf((a1.z - mu) * inv * gg1.z + ee1.z, 0.f);
    r[7] = fmaxf((a1.w - mu) * inv * gg1.w + ee1.w, 0.f);

    size_t obase = (size_t)n * HD + lane * 8;
    if (MODE == 2 || MODE == 3) {
        union { uint4 u; __nv_bfloat16 h[8]; } phu, plu;
        phu.u = *(const uint4*)(ph + obase);
        plu.u = *(const uint4*)(pl + obase);
#pragma unroll
        for (int i = 0; i < 8; i++) {
            float pv = __bfloat162float(phu.h[i]) + __bfloat162float(plu.h[i]);
            r[i] = (MODE == 2) ? (r[i] + 0.7f * pv) : (r[i] * 0.7f + pv);
        }
    }

    union { __nv_bfloat16 h[8]; uint4 u; } uh, ul;
#pragma unroll
    for (int i = 0; i < 8; i++) {
        __nv_bfloat16 hi = __float2bfloat16_rn(r[i]);
        uh.h[i] = hi;
        ul.h[i] = __float2bfloat16_rn(r[i] - __bfloat162float(hi));
    }
    *(uint4*)(oh + obase) = uh.u;
    *(uint4*)(ol + obase) = ul.u;
}

// ==================== orchestration ====================
extern "C" void kernel_launch(void* const* d_in, const int* in_sizes, int n_in,
                              void* d_out, int out_size)
{
    const float* x   = (const float*)d_in[0];
    const void*  ei  = d_in[1];
    const float* W1  = (const float*)d_in[2];
    const float* b1  = (const float*)d_in[3];
    const float* g1  = (const float*)d_in[4];
    const float* be1 = (const float*)d_in[5];
    const float* W2  = (const float*)d_in[6];
    const float* b2  = (const float*)d_in[7];
    const float* g2  = (const float*)d_in[8];
    const float* be2 = (const float*)d_in[9];
    const float* W3  = (const float*)d_in[10];
    const float* b3  = (const float*)d_in[11];
    const float* g3  = (const float*)d_in[12];
    const float* be3 = (const float*)d_in[13];
    const float* Wf1 = (const float*)d_in[14];
    const float* bf1 = (const float*)d_in[15];
    const float* Wf2 = (const float*)d_in[16];
    const float* bf2 = (const float*)d_in[17];
    float* out = (float*)d_out;

    float *xw_p;
    __nv_bfloat16 *ah, *al, *w1h, *w1l, *w2h, *w2l, *w3h, *w3l, *wf1h, *wf1l;
    cudaGetSymbolAddress((void**)&xw_p, g_xw);
    cudaGetSymbolAddress((void**)&ah, g_ah);
    cudaGetSymbolAddress((void**)&al, g_al);
    cudaGetSymbolAddress((void**)&w1h, g_w1t_h);  cudaGetSymbolAddress((void**)&w1l, g_w1t_l);
    cudaGetSymbolAddress((void**)&w2h, g_w2t_h);  cudaGetSymbolAddress((void**)&w2l, g_w2t_l);
    cudaGetSymbolAddress((void**)&w3h, g_w3t_h);  cudaGetSymbolAddress((void**)&w3l, g_w3t_l);
    cudaGetSymbolAddress((void**)&wf1h, g_wf1t_h); cudaGetSymbolAddress((void**)&wf1l, g_wf1t_l);

    const int SMEM2 = 2 * 61440;   // k_mma2: 120KB
    const int SMEMH = 2 * 40960;   // k_head: 80KB
    cudaFuncSetAttribute(k_mma2<128>, cudaFuncAttributeMaxDynamicSharedMemorySize, SMEM2);
    cudaFuncSetAttribute(k_mma2<256>, cudaFuncAttributeMaxDynamicSharedMemorySize, SMEM2);
    cudaFuncSetAttribute(k_head,      cudaFuncAttributeMaxDynamicSharedMemorySize, SMEMH);

    const int TB = 256;
    int gN = (NN + TB - 1) / TB;
    int gWarp = (NN * 32 + TB - 1) / TB;
    int mBlocks = (NN + 127) / 128;

    // #1 weight transpose+split, #2 x split, #3 detect+init
    k_wtall<<<(196608 + TB - 1) / TB, TB>>>(W1, W2, W3, Wf1,
        w1h, w1l, w2h, w2l, w3h, w3l, wf1h, wf1l);
    k_xcvt<<<(NN * 128 + TB - 1) / TB, TB>>>(x, ah, al, NN * 128);
    k_detinit<<<gN, TB>>>((const int*)ei);

    // #4 layer-1 GEMM (ncu capture target)
    k_mma2<128><<<mBlocks, 256, SMEM2>>>(ah, al, w1h, w1l, xw_p, NN);

    // #5-#7 CSR build
    k_deg<<<(NE + TB - 1) / TB, TB>>>(ei);
    k_scan<<<1, 1024>>>();
    k_fillself<<<(NN + NE + TB - 1) / TB, TB>>>(ei);

    // #8 layer-1 aggregate (writes x1 as bf16 hi/lo into ah/al)
    k_agg<1><<<gWarp, TB>>>(xw_p, b1, g1, be1, nullptr, nullptr, ah, al);

    // #9-#10 layer 2 (residual prev from ah/al, in-place)
    k_mma2<256><<<mBlocks, 256, SMEM2>>>(ah, al, w2h, w2l, xw_p, NN);
    k_agg<2><<<gWarp, TB>>>(xw_p, b2, g2, be2, ah, al, ah, al);

    // #11-#12 layer 3
    k_mma2<256><<<mBlocks, 256, SMEM2>>>(ah, al, w3h, w3l, xw_p, NN);
    k_agg<3><<<gWarp, TB>>>(xw_p, b3, g3, be3, ah, al, ah, al);

    // #13 MLP head fused with final projection
    k_head<<<mBlocks, 256, SMEMH>>>(ah, al, wf1h, wf1l, bf1, NN, Wf2, bf2, out);
}

// round 8
// speedup vs baseline: 1.1894x; 1.1894x over previous
#include <cuda_runtime.h>
#include <cuda_fp16.h>
#include <cstdint>

#define NN 50000
#define NE 800000
#define NM (NE + NN)
#define HD 256
#define EPSV 1e-5f

// ==================== PTX helpers ====================
#define LDSM4(r, addr) asm volatile( \
    "ldmatrix.sync.aligned.m8n8.x4.shared.b16 {%0,%1,%2,%3}, [%4];" \
    : "=r"((r)[0]), "=r"((r)[1]), "=r"((r)[2]), "=r"((r)[3]) : "r"(addr))

#define MMA_FP16(d, a, b0, b1) asm volatile( \
    "mma.sync.aligned.m16n8k16.row.col.f32.f16.f16.f32 " \
    "{%0,%1,%2,%3}, {%4,%5,%6,%7}, {%8,%9}, {%0,%1,%2,%3};" \
    : "+f"((d)[0]), "+f"((d)[1]), "+f"((d)[2]), "+f"((d)[3]) \
    : "r"((a)[0]), "r"((a)[1]), "r"((a)[2]), "r"((a)[3]), "r"(b0), "r"(b1))

#define CP_ASYNC16(dst, src) \
    asm volatile("cp.async.cg.shared.global [%0], [%1], 16;" :: "r"(dst), "l"(src))
#define CP_COMMIT() asm volatile("cp.async.commit_group;" ::: "memory")
#define CP_WAIT1() asm volatile("cp.async.wait_group 1;" ::: "memory")
#define CP_WAIT0() asm volatile("cp.async.wait_group 0;" ::: "memory")

__device__ __forceinline__ uint32_t smem_to_u32(const void* smem_ptr) {
    uint32_t addr;
    asm("{ .reg .u64 tmp; cvta.to.shared.u64 tmp, %1; cvt.u32.u64 %0, tmp; }"
        : "=r"(addr) : "l"(smem_ptr));
    return addr;
}

// ==================== device scratch ====================
__device__ __align__(256) float  g_xw[(size_t)NN * HD];      // GEMM out (fp32, agg gathers this)
__device__ __align__(256) __half g_af[(size_t)NN * HD];      // activations, fp16 single
__device__ __align__(256) __half g_w1t_h[256 * 128], g_w1t_l[256 * 128];
__device__ __align__(256) __half g_w2t_h[256 * 256], g_w2t_l[256 * 256];
__device__ __align__(256) __half g_w3t_h[256 * 256], g_w3t_l[256 * 256];
__device__ __align__(256) __half g_wf1t_h[128 * 256], g_wf1t_l[128 * 256];
__device__ int   g_cnt[NN];
__device__ int   g_off[NN + 1];
__device__ int   g_cur[NN];
__device__ int   g_src[NM];
__device__ float g_nrm[NM];
__device__ int   g_is64;

__device__ __forceinline__ int edge_val(const void* ei, int which, int e) {
    if (g_is64) return (int)((const long long*)ei)[(size_t)which * NE + e];
    return ((const int*)ei)[(size_t)which * NE + e];
}

// ======= fused: warp-parallel edge dtype detect + cnt/cur init =======
__global__ void k_detinit(const int* __restrict__ p) {
    int i = blockIdx.x * blockDim.x + threadIdx.x;
    if (blockIdx.x == 0 && threadIdx.x < 32) {
        int lane = threadIdx.x;
        int nz = 0;
        for (int j = lane; j < 1024; j += 32) nz |= p[2 * j + 1];
        unsigned any = __ballot_sync(0xffffffffu, nz != 0);
        if (lane == 0) g_is64 = (any == 0) ? 1 : 0;
    }
    if (i < NN) { g_cnt[i] = 1; g_cur[i] = 1; }
}

__global__ void k_deg(const void* __restrict__ ei) {
    int e = blockIdx.x * blockDim.x + threadIdx.x;
    if (e < NE) atomicAdd(&g_cnt[edge_val(ei, 1, e)], 1);
}

// single-block exclusive scan over g_cnt -> g_off
__global__ void k_scan() {
    __shared__ int s[1024];
    const int CH = (NN + 1023) / 1024;
    int tid = threadIdx.x;
    int base = tid * CH;
    int sum = 0;
    for (int i = 0; i < CH; i++) { int idx = base + i; if (idx < NN) sum += g_cnt[idx]; }
    s[tid] = sum;
    __syncthreads();
    for (int o = 1; o < 1024; o <<= 1) {
        int v = (tid >= o) ? s[tid - o] : 0;
        __syncthreads();
        s[tid] += v;
        __syncthreads();
    }
    int run = (tid == 0) ? 0 : s[tid - 1];
    for (int i = 0; i < CH; i++) {
        int idx = base + i;
        if (idx < NN) { g_off[idx] = run; run += g_cnt[idx]; }
    }
    if (tid == 1023) g_off[NN] = s[1023];
}

// ============ fused: self-loops + edge fill ============
__global__ void k_fillself(const void* __restrict__ ei) {
    int t = blockIdx.x * blockDim.x + threadIdx.x;
    if (t < NN) {
        int o = g_off[t];
        g_src[o] = t;
        g_nrm[o] = 1.0f / (float)g_cnt[t];
    } else if (t < NN + NE) {
        int e = t - NN;
        int r = edge_val(ei, 0, e);
        int c = edge_val(ei, 1, e);
        int p = atomicAdd(&g_cur[c], 1);
        int s = g_off[c] + p;
        g_src[s] = r;
        g_nrm[s] = rsqrtf((float)g_cnt[r]) * rsqrtf((float)g_cnt[c]);
    }
}

// ====== fused weight transpose + fp16 hi/lo split for all 4 weights ======
__global__ void k_wtall(
    const float* __restrict__ W1, const float* __restrict__ W2,
    const float* __restrict__ W3, const float* __restrict__ Wf1,
    __half* __restrict__ w1h, __half* __restrict__ w1l,
    __half* __restrict__ w2h, __half* __restrict__ w2l,
    __half* __restrict__ w3h, __half* __restrict__ w3l,
    __half* __restrict__ wfh, __half* __restrict__ wfl)
{
    int idx = blockIdx.x * blockDim.x + threadIdx.x;
    const float* W; __half *Th, *Tl; int K, Nc, local;
    if (idx < 32768)       { W = W1;  Th = w1h; Tl = w1l; K = 128; Nc = 256; local = idx; }
    else if (idx < 98304)  { W = W2;  Th = w2h; Tl = w2l; K = 256; Nc = 256; local = idx - 32768; }
    else if (idx < 163840) { W = W3;  Th = w3h; Tl = w3l; K = 256; Nc = 256; local = idx - 98304; }
    else if (idx < 196608) { W = Wf1; Th = wfh; Tl = wfl; K = 256; Nc = 128; local = idx - 163840; }
    else return;
    int k = local / Nc, n = local % Nc;
    float a = W[local];
    __half hi = __float2half_rn(a);
    __half lo = __float2half_rn(a - __half2float(hi));
    Th[(size_t)n * K + k] = hi;
    Tl[(size_t)n * K + k] = lo;
}

// ==================== x -> fp16 single ====================
__global__ void k_xcvt(const float* __restrict__ x, __half* __restrict__ Af, int total) {
    int idx = blockIdx.x * blockDim.x + threadIdx.x;
    if (idx >= total) return;
    Af[idx] = __float2half_rn(x[idx]);
}

// ============== fp16x2 GEMM: 32x64 warp tile, 3-stage, 2 CTAs/SM ==========
// C[M,Nc] = A[M,K] @ W[K,Nc].  A fp16 single; W fp16 hi/lo transposed.
// D = A*Wh + A*Wl (2 terms, err ~= A's fp16 rounding 2^-11).
// CTA tile 128x128, warps 4m x 2n, stage 30KB x 3, one barrier per chunk.
template<int K>
__global__ __launch_bounds__(256, 2) void k_mma(
    const __half* __restrict__ Af,
    const __half* __restrict__ Bh, const __half* __restrict__ Bl,
    float* __restrict__ C, int M, int Nc)
{
    constexpr int BK = 32;
    constexpr int NC_CHUNK = K / BK;
    constexpr int SA = BK + 8;                 // 40 halfs = 80B stride
    constexpr int QTR = 128 * SA * 2;          // 10240 B
    constexpr int STAGE = 3 * QTR;             // 30720 B (A, Bh, Bl)

    extern __shared__ char smem[];
    uint32_t smem_base = smem_to_u32(smem);
    int tid = threadIdx.x;
    int lane = tid & 31;
    int wid = tid >> 5;
    int bm = blockIdx.y * 128;
    int bn = blockIdx.x * 128;
    int wm = (wid >> 1) * 32;
    int wn = (wid & 1) * 64;
    int lt = lane >> 3;
    int lr = lane & 7;

    uint32_t a_base[2];
#pragma unroll
    for (int mi = 0; mi < 2; mi++)
        a_base[mi] = smem_base +
            ((wm + mi * 16 + (lt & 1) * 8 + lr) * SA + (lt >> 1) * 8) * 2;
    uint32_t b_base[4][2];
#pragma unroll
    for (int nj = 0; nj < 4; nj++)
#pragma unroll
        for (int w = 0; w < 2; w++)
            b_base[nj][w] = smem_base + (1 + w) * QTR +
                ((wn + nj * 16 + (lt >> 1) * 8 + lr) * SA + (lt & 1) * 8) * 2;

    auto issue_chunk = [&](int c) {
        uint32_t dst = smem_base + (uint32_t)(c % 3) * STAGE;
#pragma unroll
        for (int t = 0; t < 6; t++) {
            int i = tid + t * 256;              // 0..1535 uint4 slots
            if (i < 512) {                      // A
                int m = i >> 2, k = (i & 3) * 8;
                int gm = bm + m;
                if (gm > M - 1) gm = M - 1;     // clamp: safe reads, never stored
                CP_ASYNC16(dst + (m * SA + k) * 2,
                           Af + (size_t)gm * K + c * BK + k);
            } else if (i < 1024) {              // B hi
                int j = i - 512;
                int n = j >> 2, k = (j & 3) * 8;
                CP_ASYNC16(dst + QTR + (n * SA + k) * 2,
                           Bh + (size_t)(bn + n) * K + c * BK + k);
            } else {                            // B lo
                int j = i - 1024;
                int n = j >> 2, k = (j & 3) * 8;
                CP_ASYNC16(dst + 2 * QTR + (n * SA + k) * 2,
                           Bl + (size_t)(bn + n) * K + c * BK + k);
            }
        }
    };

    float acc[2][8][4];
#pragma unroll
    for (int mi = 0; mi < 2; mi++)
#pragma unroll
        for (int ni = 0; ni < 8; ni++)
#pragma unroll
            for (int v = 0; v < 4; v++) acc[mi][ni][v] = 0.f;

    issue_chunk(0); CP_COMMIT();
    if (NC_CHUNK > 1) { issue_chunk(1); CP_COMMIT(); }

    for (int c = 0; c < NC_CHUNK; c++) {
        if (c + 1 < NC_CHUNK) CP_WAIT1(); else CP_WAIT0();
        __syncthreads();     // data c visible; all warps done with buf (c+2)%3
        if (c + 2 < NC_CHUNK) { issue_chunk(c + 2); CP_COMMIT(); }

        uint32_t sbuf = (uint32_t)(c % 3) * STAGE;
#pragma unroll
        for (int ks = 0; ks < BK / 16; ks++) {
            uint32_t o = sbuf + ks * 32;
            uint32_t af[2][4];
            LDSM4(af[0], a_base[0] + o);
            LDSM4(af[1], a_base[1] + o);
            uint32_t bhB[2][4], blB[2][4];
            LDSM4(bhB[0], b_base[0][0] + o);
            LDSM4(blB[0], b_base[0][1] + o);
#pragma unroll
            for (int nj = 0; nj < 4; nj++) {
                int cur = nj & 1, nxt = cur ^ 1;
                if (nj < 3) {
                    LDSM4(bhB[nxt], b_base[nj + 1][0] + o);
                    LDSM4(blB[nxt], b_base[nj + 1][1] + o);
                }
                // hi term (4 MMAs) then lo term (4): same-acc gap = 4
                MMA_FP16(acc[0][2 * nj],     af[0], bhB[cur][0], bhB[cur][1]);
                MMA_FP16(acc[1][2 * nj],     af[1], bhB[cur][0], bhB[cur][1]);
                MMA_FP16(acc[0][2 * nj + 1], af[0], bhB[cur][2], bhB[cur][3]);
                MMA_FP16(acc[1][2 * nj + 1], af[1], bhB[cur][2], bhB[cur][3]);
                MMA_FP16(acc[0][2 * nj],     af[0], blB[cur][0], blB[cur][1]);
                MMA_FP16(acc[1][2 * nj],     af[1], blB[cur][0], blB[cur][1]);
                MMA_FP16(acc[0][2 * nj + 1], af[0], blB[cur][2], blB[cur][3]);
                MMA_FP16(acc[1][2 * nj + 1], af[1], blB[cur][2], blB[cur][3]);
            }
        }
    }

    // ---- epilogue ----
    int g = lane >> 2, tg = lane & 3;
#pragma unroll
    for (int mi = 0; mi < 2; mi++) {
        int r0 = bm + wm + mi * 16 + g;
#pragma unroll
        for (int ni = 0; ni < 8; ni++) {
            int col = bn + wn + ni * 8 + tg * 2;
            float2 v0 = make_float2(acc[mi][ni][0], acc[mi][ni][1]);
            float2 v1 = make_float2(acc[mi][ni][2], acc[mi][ni][3]);
            if (r0 < M)     *(float2*)(C + (size_t)r0 * Nc + col) = v0;
            if (r0 + 8 < M) *(float2*)(C + (size_t)(r0 + 8) * Nc + col) = v1;
        }
    }
}

// ======== head GEMM with fused relu + Wf2 reduction (fp16x2) ========
// out[m] = sum_col relu( (A@Wf1)[m,col] + bf1[col] ) * Wf2[col] + bf2
__global__ __launch_bounds__(256, 2) void k_head(
    const __half* __restrict__ Af,
    const __half* __restrict__ Bh, const __half* __restrict__ Bl,
    const float* __restrict__ bias, int M,
    const float* __restrict__ wf2, const float* __restrict__ bf2,
    float* __restrict__ outp)
{
    constexpr int K = 256;
    constexpr int BK = 32;
    constexpr int NC_CHUNK = K / BK;
    constexpr int SA = BK + 8;
    constexpr int QTR = 128 * SA * 2;
    constexpr int STAGE = 3 * QTR;

    extern __shared__ char smem[];
    __shared__ float red[128];
    uint32_t smem_base = smem_to_u32(smem);
    int tid = threadIdx.x;
    int lane = tid & 31;
    int wid = tid >> 5;
    int bm = blockIdx.x * 128;
    int wm = (wid >> 1) * 32;
    int wn = (wid & 1) * 64;
    int lt = lane >> 3;
    int lr = lane & 7;

    if (tid < 128) red[tid] = 0.f;

    uint32_t a_base[2];
#pragma unroll
    for (int mi = 0; mi < 2; mi++)
        a_base[mi] = smem_base +
            ((wm + mi * 16 + (lt & 1) * 8 + lr) * SA + (lt >> 1) * 8) * 2;
    uint32_t b_base[4][2];
#pragma unroll
    for (int nj = 0; nj < 4; nj++)
#pragma unroll
        for (int w = 0; w < 2; w++)
            b_base[nj][w] = smem_base + (1 + w) * QTR +
                ((wn + nj * 16 + (lt >> 1) * 8 + lr) * SA + (lt & 1) * 8) * 2;

    auto issue_chunk = [&](int c) {
        uint32_t dst = smem_base + (uint32_t)(c % 3) * STAGE;
#pragma unroll
        for (int t = 0; t < 6; t++) {
            int i = tid + t * 256;
            if (i < 512) {
                int m = i >> 2, k = (i & 3) * 8;
                int gm = bm + m;
                if (gm > M - 1) gm = M - 1;
                CP_ASYNC16(dst + (m * SA + k) * 2,
                           Af + (size_t)gm * K + c * BK + k);
            } else if (i < 1024) {
                int j = i - 512;
                int n = j >> 2, k = (j & 3) * 8;
                CP_ASYNC16(dst + QTR + (n * SA + k) * 2,
                           Bh + (size_t)n * K + c * BK + k);   // Nc=128, bn=0
            } else {
                int j = i - 1024;
                int n = j >> 2, k = (j & 3) * 8;
                CP_ASYNC16(dst + 2 * QTR + (n * SA + k) * 2,
                           Bl + (size_t)n * K + c * BK + k);
            }
        }
    };

    float acc[2][8][4];
#pragma unroll
    for (int mi = 0; mi < 2; mi++)
#pragma unroll
        for (int ni = 0; ni < 8; ni++)
#pragma unroll
            for (int v = 0; v < 4; v++) acc[mi][ni][v] = 0.f;

    issue_chunk(0); CP_COMMIT();
    issue_chunk(1); CP_COMMIT();

    for (int c = 0; c < NC_CHUNK; c++) {
        if (c + 1 < NC_CHUNK) CP_WAIT1(); else CP_WAIT0();
        __syncthreads();
        if (c + 2 < NC_CHUNK) { issue_chunk(c + 2); CP_COMMIT(); }

        uint32_t sbuf = (uint32_t)(c % 3) * STAGE;
#pragma unroll
        for (int ks = 0; ks < BK / 16; ks++) {
            uint32_t o = sbuf + ks * 32;
            uint32_t af[2][4];
            LDSM4(af[0], a_base[0] + o);
            LDSM4(af[1], a_base[1] + o);
            uint32_t bhB[2][4], blB[2][4];
            LDSM4(bhB[0], b_base[0][0] + o);
            LDSM4(blB[0], b_base[0][1] + o);
#pragma unroll
            for (int nj = 0; nj < 4; nj++) {
                int cur = nj & 1, nxt = cur ^ 1;
                if (nj < 3) {
                    LDSM4(bhB[nxt], b_base[nj + 1][0] + o);
                    LDSM4(blB[nxt], b_base[nj + 1][1] + o);
                }
                MMA_FP16(acc[0][2 * nj],     af[0], bhB[cur][0], bhB[cur][1]);
                MMA_FP16(acc[1][2 * nj],     af[1], bhB[cur][0], bhB[cur][1]);
                MMA_FP16(acc[0][2 * nj + 1], af[0], bhB[cur][2], bhB[cur][3]);
                MMA_FP16(acc[1][2 * nj + 1], af[1], bhB[cur][2], bhB[cur][3]);
                MMA_FP16(acc[0][2 * nj],     af[0], blB[cur][0], blB[cur][1]);
                MMA_FP16(acc[1][2 * nj],     af[1], blB[cur][0], blB[cur][1]);
                MMA_FP16(acc[0][2 * nj + 1], af[0], blB[cur][2], blB[cur][3]);
                MMA_FP16(acc[1][2 * nj + 1], af[1], blB[cur][2], blB[cur][3]);
            }
        }
    }

    int g = lane >> 2, tg = lane & 3;
    __syncthreads();
#pragma unroll
    for (int mi = 0; mi < 2; mi++) {
        float p0 = 0.f, p1 = 0.f;
#pragma unroll
        for (int ni = 0; ni < 8; ni++) {
            int col = wn + ni * 8 + tg * 2;
            float bx = bias[col], by = bias[col + 1];
            float w0 = wf2[col], w1 = wf2[col + 1];
            p0 += fmaxf(acc[mi][ni][0] + bx, 0.f) * w0
                + fmaxf(acc[mi][ni][1] + by, 0.f) * w1;
            p1 += fmaxf(acc[mi][ni][2] + bx, 0.f) * w0
                + fmaxf(acc[mi][ni][3] + by, 0.f) * w1;
        }
        atomicAdd(&red[wm + mi * 16 + g], p0);
        atomicAdd(&red[wm + mi * 16 + 8 + g], p1);
    }
    __syncthreads();
    if (tid < 128) {
        int r = bm + tid;
        if (r < M) outp[r] = red[tid] + bf2[0];
    }
}

// ======== fused aggregate(+bias)+LN+ReLU+residual -> fp16 single ========
template<int MODE>
__global__ __launch_bounds__(256) void k_agg(
    const float* __restrict__ xw, const float* __restrict__ bias,
    const float* __restrict__ gam, const float* __restrict__ bet,
    const __half* __restrict__ prev, __half* __restrict__ outp)
{
    int n = (blockIdx.x * blockDim.x + threadIdx.x) >> 5;
    int lane = threadIdx.x & 31;
    if (n >= NN) return;
    int s0 = g_off[n], s1 = g_off[n + 1];
    float4 a0 = make_float4(0.f, 0.f, 0.f, 0.f);
    float4 a1 = make_float4(0.f, 0.f, 0.f, 0.f);
    int s = s0;
    for (; s + 3 < s1; s += 4) {
        int i0 = g_src[s], i1 = g_src[s + 1], i2 = g_src[s + 2], i3 = g_src[s + 3];
        float w0 = g_nrm[s], w1 = g_nrm[s + 1], w2 = g_nrm[s + 2], w3 = g_nrm[s + 3];
        const float4* p0 = (const float4*)(xw + (size_t)i0 * HD) + (lane << 1);
        const float4* p1 = (const float4*)(xw + (size_t)i1 * HD) + (lane << 1);
        const float4* p2 = (const float4*)(xw + (size_t)i2 * HD) + (lane << 1);
        const float4* p3 = (const float4*)(xw + (size_t)i3 * HD) + (lane << 1);
        float4 u0 = p0[0], u1 = p0[1];
        float4 v0 = p1[0], v1 = p1[1];
        float4 q0 = p2[0], q1 = p2[1];
        float4 t0 = p3[0], t1 = p3[1];
        a0.x += w0 * u0.x; a0.y += w0 * u0.y; a0.z += w0 * u0.z; a0.w += w0 * u0.w;
        a1.x += w0 * u1.x; a1.y += w0 * u1.y; a1.z += w0 * u1.z; a1.w += w0 * u1.w;
        a0.x += w1 * v0.x; a0.y += w1 * v0.y; a0.z += w1 * v0.z; a0.w += w1 * v0.w;
        a1.x += w1 * v1.x; a1.y += w1 * v1.y; a1.z += w1 * v1.z; a1.w += w1 * v1.w;
        a0.x += w2 * q0.x; a0.y += w2 * q0.y; a0.z += w2 * q0.z; a0.w += w2 * q0.w;
        a1.x += w2 * q1.x; a1.y += w2 * q1.y; a1.z += w2 * q1.z; a1.w += w2 * q1.w;
        a0.x += w3 * t0.x; a0.y += w3 * t0.y; a0.z += w3 * t0.z; a0.w += w3 * t0.w;
        a1.x += w3 * t1.x; a1.y += w3 * t1.y; a1.z += w3 * t1.z; a1.w += w3 * t1.w;
    }
    for (; s < s1; s++) {
        int src = g_src[s];
        float w = g_nrm[s];
        const float4* p = (const float4*)(xw + (size_t)src * HD) + (lane << 1);
        float4 v0 = p[0], v1 = p[1];
        a0.x += w * v0.x; a0.y += w * v0.y; a0.z += w * v0.z; a0.w += w * v0.w;
        a1.x += w * v1.x; a1.y += w * v1.y; a1.z += w * v1.z; a1.w += w * v1.w;
    }
    const float4* bp = (const float4*)bias + (lane << 1);
    float4 b0 = bp[0], b1 = bp[1];
    a0.x += b0.x; a0.y += b0.y; a0.z += b0.z; a0.w += b0.w;
    a1.x += b1.x; a1.y += b1.y; a1.z += b1.z; a1.w += b1.w;

    float sm = a0.x + a0.y + a0.z + a0.w + a1.x + a1.y + a1.z + a1.w;
    float sq = a0.x * a0.x + a0.y * a0.y + a0.z * a0.z + a0.w * a0.w
             + a1.x * a1.x + a1.y * a1.y + a1.z * a1.z + a1.w * a1.w;
#pragma unroll
    for (int o = 16; o > 0; o >>= 1) {
        sm += __shfl_xor_sync(0xffffffffu, sm, o);
        sq += __shfl_xor_sync(0xffffffffu, sq, o);
    }
    float mu = sm * (1.f / HD);
    float inv = rsqrtf(sq * (1.f / HD) - mu * mu + EPSV);

    const float4* gp = (const float4*)gam + (lane << 1);
    const float4* ep = (const float4*)bet + (lane << 1);
    float4 gg0 = gp[0], gg1 = gp[1], ee0 = ep[0], ee1 = ep[1];
    float r[8];
    r[0] = fmaxf((a0.x - mu) * inv * gg0.x + ee0.x, 0.f);
    r[1] = fmaxf((a0.y - mu) * inv * gg0.y + ee0.y, 0.f);
    r[2] = fmaxf((a0.z - mu) * inv * gg0.z + ee0.z, 0.f);
    r[3] = fmaxf((a0.w - mu) * inv * gg0.w + ee0.w, 0.f);
    r[4] = fmaxf((a1.x - mu) * inv * gg1.x + ee1.x, 0.f);
    r[5] = fmaxf((a1.y - mu) * inv * gg1.y + ee1.y, 0.f);
    r[6] = fmaxf((a1.z - mu) * inv * gg1.z + ee1.z, 0.f);
    r[7] = fmaxf((a1.w - mu) * inv * gg1.w + ee1.w, 0.f);

    size_t obase = (size_t)n * HD + lane * 8;
    if (MODE == 2 || MODE == 3) {
        union { uint4 u; __half h[8]; } pu;
        pu.u = *(const uint4*)(prev + obase);
#pragma unroll
        for (int i = 0; i < 8; i++) {
            float pv = __half2float(pu.h[i]);
            r[i] = (MODE == 2) ? (r[i] + 0.7f * pv) : (r[i] * 0.7f + pv);
        }
    }

    union { __half h[8]; uint4 u; } uo;
#pragma unroll
    for (int i = 0; i < 8; i++) uo.h[i] = __float2half_rn(r[i]);
    *(uint4*)(outp + obase) = uo.u;
}

// ==================== orchestration ====================
extern "C" void kernel_launch(void* const* d_in, const int* in_sizes, int n_in,
                              void* d_out, int out_size)
{
    const float* x   = (const float*)d_in[0];
    const void*  ei  = d_in[1];
    const float* W1  = (const float*)d_in[2];
    const float* b1  = (const float*)d_in[3];
    const float* g1  = (const float*)d_in[4];
    const float* be1 = (const float*)d_in[5];
    const float* W2  = (const float*)d_in[6];
    const float* b2  = (const float*)d_in[7];
    const float* g2  = (const float*)d_in[8];
    const float* be2 = (const float*)d_in[9];
    const float* W3  = (const float*)d_in[10];
    const float* b3  = (const float*)d_in[11];
    const float* g3  = (const float*)d_in[12];
    const float* be3 = (const float*)d_in[13];
    const float* Wf1 = (const float*)d_in[14];
    const float* bf1 = (const float*)d_in[15];
    const float* Wf2 = (const float*)d_in[16];
    const float* bf2 = (const float*)d_in[17];
    float* out = (float*)d_out;

    float* xw_p;
    __half *af, *w1h, *w1l, *w2h, *w2l, *w3h, *w3l, *wf1h, *wf1l;
    cudaGetSymbolAddress((void**)&xw_p, g_xw);
    cudaGetSymbolAddress((void**)&af, g_af);
    cudaGetSymbolAddress((void**)&w1h, g_w1t_h);  cudaGetSymbolAddress((void**)&w1l, g_w1t_l);
    cudaGetSymbolAddress((void**)&w2h, g_w2t_h);  cudaGetSymbolAddress((void**)&w2l, g_w2t_l);
    cudaGetSymbolAddress((void**)&w3h, g_w3t_h);  cudaGetSymbolAddress((void**)&w3l, g_w3t_l);
    cudaGetSymbolAddress((void**)&wf1h, g_wf1t_h); cudaGetSymbolAddress((void**)&wf1l, g_wf1t_l);

    const int SMEM = 3 * 30720;   // 3 stages x 30KB = 92160 B
    cudaFuncSetAttribute(k_mma<128>, cudaFuncAttributeMaxDynamicSharedMemorySize, SMEM);
    cudaFuncSetAttribute(k_mma<256>, cudaFuncAttributeMaxDynamicSharedMemorySize, SMEM);
    cudaFuncSetAttribute(k_head,     cudaFuncAttributeMaxDynamicSharedMemorySize, SMEM);

    const int TB = 256;
    int gN = (NN + TB - 1) / TB;
    int gWarp = (NN * 32 + TB - 1) / TB;
    int mBlocks = (NN + 127) / 128;

    // #1 weight transpose+split, #2 x -> fp16, #3 detect+init
    k_wtall<<<(196608 + TB - 1) / TB, TB>>>(W1, W2, W3, Wf1,
        w1h, w1l, w2h, w2l, w3h, w3l, wf1h, wf1l);
    k_xcvt<<<(NN * 128 + TB - 1) / TB, TB>>>(x, af, NN * 128);
    k_detinit<<<gN, TB>>>((const int*)ei);

    // #4 layer-1 GEMM (ncu capture target)
    k_mma<128><<<dim3(2, mBlocks), 256, SMEM>>>(af, w1h, w1l, xw_p, NN, 256);

    // #5-#7 CSR build
    k_deg<<<(NE + TB - 1) / TB, TB>>>(ei);
    k_scan<<<1, 1024>>>();
    k_fillself<<<(NN + NE + TB - 1) / TB, TB>>>(ei);

    // #8 layer-1 aggregate (writes x1 fp16 into af)
    k_agg<1><<<gWarp, TB>>>(xw_p, b1, g1, be1, nullptr, af);

    // #9-#10 layer 2 (residual prev from af, in-place)
    k_mma<256><<<dim3(2, mBlocks), 256, SMEM>>>(af, w2h, w2l, xw_p, NN, 256);
    k_agg<2><<<gWarp, TB>>>(xw_p, b2, g2, be2, af, af);

    // #11-#12 layer 3
    k_mma<256><<<dim3(2, mBlocks), 256, SMEM>>>(af, w3h, w3l, xw_p, NN, 256);
    k_agg<3><<<gWarp, TB>>>(xw_p, b3, g3, be3, af, af);

    // #13 MLP head fused with final projection
    k_head<<<mBlocks, 256, SMEM>>>(af, wf1h, wf1l, bf1, NN, Wf2, bf2, out);
}

// round 9
// speedup vs baseline: 1.5204x; 1.2783x over previous
#include <cuda_runtime.h>
#include <cuda_fp16.h>
#include <cstdint>

#define NN 50000
#define NE 800000
#define NM (NE + NN)
#define HD 256
#define EPSV 1e-5f

// ==================== PTX helpers ====================
#define LDSM4(r, addr) asm volatile( \
    "ldmatrix.sync.aligned.m8n8.x4.shared.b16 {%0,%1,%2,%3}, [%4];" \
    : "=r"((r)[0]), "=r"((r)[1]), "=r"((r)[2]), "=r"((r)[3]) : "r"(addr))

#define MMA_FP16(d, a, b0, b1) asm volatile( \
    "mma.sync.aligned.m16n8k16.row.col.f32.f16.f16.f32 " \
    "{%0,%1,%2,%3}, {%4,%5,%6,%7}, {%8,%9}, {%0,%1,%2,%3};" \
    : "+f"((d)[0]), "+f"((d)[1]), "+f"((d)[2]), "+f"((d)[3]) \
    : "r"((a)[0]), "r"((a)[1]), "r"((a)[2]), "r"((a)[3]), "r"(b0), "r"(b1))

#define CP_ASYNC16(dst, src) \
    asm volatile("cp.async.cg.shared.global [%0], [%1], 16;" :: "r"(dst), "l"(src))
#define CP_COMMIT() asm volatile("cp.async.commit_group;" ::: "memory")
#define CP_WAIT1() asm volatile("cp.async.wait_group 1;" ::: "memory")
#define CP_WAIT0() asm volatile("cp.async.wait_group 0;" ::: "memory")

__device__ __forceinline__ uint32_t smem_to_u32(const void* smem_ptr) {
    uint32_t addr;
    asm("{ .reg .u64 tmp; cvta.to.shared.u64 tmp, %1; cvt.u32.u64 %0, tmp; }"
        : "=r"(addr) : "l"(smem_ptr));
    return addr;
}

// ==================== device scratch ====================
__device__ __align__(256) __half g_xw[(size_t)NN * HD];      // GEMM out, fp16 (agg gathers this)
__device__ __align__(256) __half g_af[(size_t)NN * HD];      // activations, fp16
__device__ __align__(256) __half g_w1t_h[256 * 128], g_w1t_l[256 * 128];
__device__ __align__(256) __half g_w2t_h[256 * 256], g_w2t_l[256 * 256];
__device__ __align__(256) __half g_w3t_h[256 * 256], g_w3t_l[256 * 256];
__device__ __align__(256) __half g_wf1t_h[128 * 256], g_wf1t_l[128 * 256];
__device__ int   g_cnt[NN];
__device__ int   g_off[NN + 1];
__device__ int   g_cur[NN];
__device__ int   g_src[NM];
__device__ float g_nrm[NM];
__device__ int   g_is64;

__device__ __forceinline__ int edge_val(const void* ei, int which, int e) {
    if (g_is64) return (int)((const long long*)ei)[(size_t)which * NE + e];
    return ((const int*)ei)[(size_t)which * NE + e];
}

// ======= fused: warp-parallel edge dtype detect + cnt/cur init =======
__global__ void k_detinit(const int* __restrict__ p) {
    int i = blockIdx.x * blockDim.x + threadIdx.x;
    if (blockIdx.x == 0 && threadIdx.x < 32) {
        int lane = threadIdx.x;
        int nz = 0;
        for (int j = lane; j < 1024; j += 32) nz |= p[2 * j + 1];
        unsigned any = __ballot_sync(0xffffffffu, nz != 0);
        if (lane == 0) g_is64 = (any == 0) ? 1 : 0;
    }
    if (i < NN) { g_cnt[i] = 1; g_cur[i] = 1; }
}

__global__ void k_deg(const void* __restrict__ ei) {
    int e = blockIdx.x * blockDim.x + threadIdx.x;
    if (e < NE) atomicAdd(&g_cnt[edge_val(ei, 1, e)], 1);
}

// single-block exclusive scan over g_cnt -> g_off
__global__ void k_scan() {
    __shared__ int s[1024];
    const int CH = (NN + 1023) / 1024;
    int tid = threadIdx.x;
    int base = tid * CH;
    int sum = 0;
    for (int i = 0; i < CH; i++) { int idx = base + i; if (idx < NN) sum += g_cnt[idx]; }
    s[tid] = sum;
    __syncthreads();
    for (int o = 1; o < 1024; o <<= 1) {
        int v = (tid >= o) ? s[tid - o] : 0;
        __syncthreads();
        s[tid] += v;
        __syncthreads();
    }
    int run = (tid == 0) ? 0 : s[tid - 1];
    for (int i = 0; i < CH; i++) {
        int idx = base + i;
        if (idx < NN) { g_off[idx] = run; run += g_cnt[idx]; }
    }
    if (tid == 1023) g_off[NN] = s[1023];
}

// ============ fused: self-loops + edge fill ============
__global__ void k_fillself(const void* __restrict__ ei) {
    int t = blockIdx.x * blockDim.x + threadIdx.x;
    if (t < NN) {
        int o = g_off[t];
        g_src[o] = t;
        g_nrm[o] = 1.0f / (float)g_cnt[t];
    } else if (t < NN + NE) {
        int e = t - NN;
        int r = edge_val(ei, 0, e);
        int c = edge_val(ei, 1, e);
        int p = atomicAdd(&g_cur[c], 1);
        int s = g_off[c] + p;
        g_src[s] = r;
        g_nrm[s] = rsqrtf((float)g_cnt[r]) * rsqrtf((float)g_cnt[c]);
    }
}

// ====== fused weight transpose + fp16 hi/lo split for all 4 weights ======
__global__ void k_wtall(
    const float* __restrict__ W1, const float* __restrict__ W2,
    const float* __restrict__ W3, const float* __restrict__ Wf1,
    __half* __restrict__ w1h, __half* __restrict__ w1l,
    __half* __restrict__ w2h, __half* __restrict__ w2l,
    __half* __restrict__ w3h, __half* __restrict__ w3l,
    __half* __restrict__ wfh, __half* __restrict__ wfl)
{
    int idx = blockIdx.x * blockDim.x + threadIdx.x;
    const float* W; __half *Th, *Tl; int K, Nc, local;
    if (idx < 32768)       { W = W1;  Th = w1h; Tl = w1l; K = 128; Nc = 256; local = idx; }
    else if (idx < 98304)  { W = W2;  Th = w2h; Tl = w2l; K = 256; Nc = 256; local = idx - 32768; }
    else if (idx < 163840) { W = W3;  Th = w3h; Tl = w3l; K = 256; Nc = 256; local = idx - 98304; }
    else if (idx < 196608) { W = Wf1; Th = wfh; Tl = wfl; K = 256; Nc = 128; local = idx - 163840; }
    else return;
    int k = local / Nc, n = local % Nc;
    float a = W[local];
    __half hi = __float2half_rn(a);
    __half lo = __float2half_rn(a - __half2float(hi));
    Th[(size_t)n * K + k] = hi;
    Tl[(size_t)n * K + k] = lo;
}

// ==================== x -> fp16 single ====================
__global__ void k_xcvt(const float* __restrict__ x, __half* __restrict__ Af, int total) {
    int idx = blockIdx.x * blockDim.x + threadIdx.x;
    if (idx >= total) return;
    Af[idx] = __float2half_rn(x[idx]);
}

// ============== fp16x2 GEMM: 32x64 warp tile, 3-stage, 2 CTAs/SM ==========
// C[M,Nc](fp16) = A[M,K] @ W[K,Nc].  A fp16; W fp16 hi/lo transposed.
template<int K>
__global__ __launch_bounds__(256, 2) void k_mma(
    const __half* __restrict__ Af,
    const __half* __restrict__ Bh, const __half* __restrict__ Bl,
    __half* __restrict__ C, int M, int Nc)
{
    constexpr int BK = 32;
    constexpr int NC_CHUNK = K / BK;
    constexpr int SA = BK + 8;
    constexpr int QTR = 128 * SA * 2;          // 10240 B
    constexpr int STAGE = 3 * QTR;             // 30720 B

    extern __shared__ char smem[];
    uint32_t smem_base = smem_to_u32(smem);
    int tid = threadIdx.x;
    int lane = tid & 31;
    int wid = tid >> 5;
    int bm = blockIdx.y * 128;
    int bn = blockIdx.x * 128;
    int wm = (wid >> 1) * 32;
    int wn = (wid & 1) * 64;
    int lt = lane >> 3;
    int lr = lane & 7;

    uint32_t a_base[2];
#pragma unroll
    for (int mi = 0; mi < 2; mi++)
        a_base[mi] = smem_base +
            ((wm + mi * 16 + (lt & 1) * 8 + lr) * SA + (lt >> 1) * 8) * 2;
    uint32_t b_base[4][2];
#pragma unroll
    for (int nj = 0; nj < 4; nj++)
#pragma unroll
        for (int w = 0; w < 2; w++)
            b_base[nj][w] = smem_base + (1 + w) * QTR +
                ((wn + nj * 16 + (lt >> 1) * 8 + lr) * SA + (lt & 1) * 8) * 2;

    auto issue_chunk = [&](int c) {
        uint32_t dst = smem_base + (uint32_t)(c % 3) * STAGE;
#pragma unroll
        for (int t = 0; t < 6; t++) {
            int i = tid + t * 256;
            if (i < 512) {
                int m = i >> 2, k = (i & 3) * 8;
                int gm = bm + m;
                if (gm > M - 1) gm = M - 1;
                CP_ASYNC16(dst + (m * SA + k) * 2,
                           Af + (size_t)gm * K + c * BK + k);
            } else if (i < 1024) {
                int j = i - 512;
                int n = j >> 2, k = (j & 3) * 8;
                CP_ASYNC16(dst + QTR + (n * SA + k) * 2,
                           Bh + (size_t)(bn + n) * K + c * BK + k);
            } else {
                int j = i - 1024;
                int n = j >> 2, k = (j & 3) * 8;
                CP_ASYNC16(dst + 2 * QTR + (n * SA + k) * 2,
                           Bl + (size_t)(bn + n) * K + c * BK + k);
            }
        }
    };

    float acc[2][8][4];
#pragma unroll
    for (int mi = 0; mi < 2; mi++)
#pragma unroll
        for (int ni = 0; ni < 8; ni++)
#pragma unroll
            for (int v = 0; v < 4; v++) acc[mi][ni][v] = 0.f;

    issue_chunk(0); CP_COMMIT();
    if (NC_CHUNK > 1) { issue_chunk(1); CP_COMMIT(); }

    for (int c = 0; c < NC_CHUNK; c++) {
        if (c + 1 < NC_CHUNK) CP_WAIT1(); else CP_WAIT0();
        __syncthreads();
        if (c + 2 < NC_CHUNK) { issue_chunk(c + 2); CP_COMMIT(); }

        uint32_t sbuf = (uint32_t)(c % 3) * STAGE;
#pragma unroll
        for (int ks = 0; ks < BK / 16; ks++) {
            uint32_t o = sbuf + ks * 32;
            uint32_t af[2][4];
            LDSM4(af[0], a_base[0] + o);
            LDSM4(af[1], a_base[1] + o);
            uint32_t bhB[2][4], blB[2][4];
            LDSM4(bhB[0], b_base[0][0] + o);
            LDSM4(blB[0], b_base[0][1] + o);
#pragma unroll
            for (int nj = 0; nj < 4; nj++) {
                int cur = nj & 1, nxt = cur ^ 1;
                if (nj < 3) {
                    LDSM4(bhB[nxt], b_base[nj + 1][0] + o);
                    LDSM4(blB[nxt], b_base[nj + 1][1] + o);
                }
                MMA_FP16(acc[0][2 * nj],     af[0], bhB[cur][0], bhB[cur][1]);
                MMA_FP16(acc[1][2 * nj],     af[1], bhB[cur][0], bhB[cur][1]);
                MMA_FP16(acc[0][2 * nj + 1], af[0], bhB[cur][2], bhB[cur][3]);
                MMA_FP16(acc[1][2 * nj + 1], af[1], bhB[cur][2], bhB[cur][3]);
                MMA_FP16(acc[0][2 * nj],     af[0], blB[cur][0], blB[cur][1]);
                MMA_FP16(acc[1][2 * nj],     af[1], blB[cur][0], blB[cur][1]);
                MMA_FP16(acc[0][2 * nj + 1], af[0], blB[cur][2], blB[cur][3]);
                MMA_FP16(acc[1][2 * nj + 1], af[1], blB[cur][2], blB[cur][3]);
            }
        }
    }

    // ---- epilogue: fp16 stores (half2 per acc pair) ----
    int g = lane >> 2, tg = lane & 3;
#pragma unroll
    for (int mi = 0; mi < 2; mi++) {
        int r0 = bm + wm + mi * 16 + g;
#pragma unroll
        for (int ni = 0; ni < 8; ni++) {
            int col = bn + wn + ni * 8 + tg * 2;
            __half2 v0 = __floats2half2_rn(acc[mi][ni][0], acc[mi][ni][1]);
            __half2 v1 = __floats2half2_rn(acc[mi][ni][2], acc[mi][ni][3]);
            if (r0 < M)     *(__half2*)(C + (size_t)r0 * Nc + col) = v0;
            if (r0 + 8 < M) *(__half2*)(C + (size_t)(r0 + 8) * Nc + col) = v1;
        }
    }
}

// ======== head GEMM with fused relu + Wf2 reduction (fp16x2) ========
__global__ __launch_bounds__(256, 2) void k_head(
    const __half* __restrict__ Af,
    const __half* __restrict__ Bh, const __half* __restrict__ Bl,
    const float* __restrict__ bias, int M,
    const float* __restrict__ wf2, const float* __restrict__ bf2,
    float* __restrict__ outp)
{
    constexpr int K = 256;
    constexpr int BK = 32;
    constexpr int NC_CHUNK = K / BK;
    constexpr int SA = BK + 8;
    constexpr int QTR = 128 * SA * 2;
    constexpr int STAGE = 3 * QTR;

    extern __shared__ char smem[];
    __shared__ float red[128];
    uint32_t smem_base = smem_to_u32(smem);
    int tid = threadIdx.x;
    int lane = tid & 31;
    int wid = tid >> 5;
    int bm = blockIdx.x * 128;
    int wm = (wid >> 1) * 32;
    int wn = (wid & 1) * 64;
    int lt = lane >> 3;
    int lr = lane & 7;

    if (tid < 128) red[tid] = 0.f;

    uint32_t a_base[2];
#pragma unroll
    for (int mi = 0; mi < 2; mi++)
        a_base[mi] = smem_base +
            ((wm + mi * 16 + (lt & 1) * 8 + lr) * SA + (lt >> 1) * 8) * 2;
    uint32_t b_base[4][2];
#pragma unroll
    for (int nj = 0; nj < 4; nj++)
#pragma unroll
        for (int w = 0; w < 2; w++)
            b_base[nj][w] = smem_base + (1 + w) * QTR +
                ((wn + nj * 16 + (lt >> 1) * 8 + lr) * SA + (lt & 1) * 8) * 2;

    auto issue_chunk = [&](int c) {
        uint32_t dst = smem_base + (uint32_t)(c % 3) * STAGE;
#pragma unroll
        for (int t = 0; t < 6; t++) {
            int i = tid + t * 256;
            if (i < 512) {
                int m = i >> 2, k = (i & 3) * 8;
                int gm = bm + m;
                if (gm > M - 1) gm = M - 1;
                CP_ASYNC16(dst + (m * SA + k) * 2,
                           Af + (size_t)gm * K + c * BK + k);
            } else if (i < 1024) {
                int j = i - 512;
                int n = j >> 2, k = (j & 3) * 8;
                CP_ASYNC16(dst + QTR + (n * SA + k) * 2,
                           Bh + (size_t)n * K + c * BK + k);
            } else {
                int j = i - 1024;
                int n = j >> 2, k = (j & 3) * 8;
                CP_ASYNC16(dst + 2 * QTR + (n * SA + k) * 2,
                           Bl + (size_t)n * K + c * BK + k);
            }
        }
    };

    float acc[2][8][4];
#pragma unroll
    for (int mi = 0; mi < 2; mi++)
#pragma unroll
        for (int ni = 0; ni < 8; ni++)
#pragma unroll
            for (int v = 0; v < 4; v++) acc[mi][ni][v] = 0.f;

    issue_chunk(0); CP_COMMIT();
    issue_chunk(1); CP_COMMIT();

    for (int c = 0; c < NC_CHUNK; c++) {
        if (c + 1 < NC_CHUNK) CP_WAIT1(); else CP_WAIT0();
        __syncthreads();
        if (c + 2 < NC_CHUNK) { issue_chunk(c + 2); CP_COMMIT(); }

        uint32_t sbuf = (uint32_t)(c % 3) * STAGE;
#pragma unroll
        for (int ks = 0; ks < BK / 16; ks++) {
            uint32_t o = sbuf + ks * 32;
            uint32_t af[2][4];
            LDSM4(af[0], a_base[0] + o);
            LDSM4(af[1], a_base[1] + o);
            uint32_t bhB[2][4], blB[2][4];
            LDSM4(bhB[0], b_base[0][0] + o);
            LDSM4(blB[0], b_base[0][1] + o);
#pragma unroll
            for (int nj = 0; nj < 4; nj++) {
                int cur = nj & 1, nxt = cur ^ 1;
                if (nj < 3) {
                    LDSM4(bhB[nxt], b_base[nj + 1][0] + o);
                    LDSM4(blB[nxt], b_base[nj + 1][1] + o);
                }
                MMA_FP16(acc[0][2 * nj],     af[0], bhB[cur][0], bhB[cur][1]);
                MMA_FP16(acc[1][2 * nj],     af[1], bhB[cur][0], bhB[cur][1]);
                MMA_FP16(acc[0][2 * nj + 1], af[0], bhB[cur][2], bhB[cur][3]);
                MMA_FP16(acc[1][2 * nj + 1], af[1], bhB[cur][2], bhB[cur][3]);
                MMA_FP16(acc[0][2 * nj],     af[0], blB[cur][0], blB[cur][1]);
                MMA_FP16(acc[1][2 * nj],     af[1], blB[cur][0], blB[cur][1]);
                MMA_FP16(acc[0][2 * nj + 1], af[0], blB[cur][2], blB[cur][3]);
                MMA_FP16(acc[1][2 * nj + 1], af[1], blB[cur][2], blB[cur][3]);
            }
        }
    }

    int g = lane >> 2, tg = lane & 3;
    __syncthreads();
#pragma unroll
    for (int mi = 0; mi < 2; mi++) {
        float p0 = 0.f, p1 = 0.f;
#pragma unroll
        for (int ni = 0; ni < 8; ni++) {
            int col = wn + ni * 8 + tg * 2;
            float bx = bias[col], by = bias[col + 1];
            float w0 = wf2[col], w1 = wf2[col + 1];
            p0 += fmaxf(acc[mi][ni][0] + bx, 0.f) * w0
                + fmaxf(acc[mi][ni][1] + by, 0.f) * w1;
            p1 += fmaxf(acc[mi][ni][2] + bx, 0.f) * w0
                + fmaxf(acc[mi][ni][3] + by, 0.f) * w1;
        }
        atomicAdd(&red[wm + mi * 16 + g], p0);
        atomicAdd(&red[wm + mi * 16 + 8 + g], p1);
    }
    __syncthreads();
    if (tid < 128) {
        int r = bm + tid;
        if (r < M) outp[r] = red[tid] + bf2[0];
    }
}

// ======== fused aggregate(+bias)+LN+ReLU+residual, fp16 gather ========
// xw is fp16: each lane reads ONE uint4 (8 halfs) per neighbor row (512B/row).
template<int MODE>
__global__ __launch_bounds__(256) void k_agg(
    const __half* __restrict__ xw, const float* __restrict__ bias,
    const float* __restrict__ gam, const float* __restrict__ bet,
    const __half* __restrict__ prev, __half* __restrict__ outp)
{
    int n = (blockIdx.x * blockDim.x + threadIdx.x) >> 5;
    int lane = threadIdx.x & 31;
    if (n >= NN) return;
    int s0 = g_off[n], s1 = g_off[n + 1];
    float a[8] = {0.f, 0.f, 0.f, 0.f, 0.f, 0.f, 0.f, 0.f};
    int s = s0;

    auto accum = [&](uint4 raw, float w) {
        union { uint4 u; __half2 h[4]; } cv;
        cv.u = raw;
#pragma unroll
        for (int q = 0; q < 4; q++) {
            float2 f = __half22float2(cv.h[q]);
            a[2 * q]     += w * f.x;
            a[2 * q + 1] += w * f.y;
        }
    };

    for (; s + 3 < s1; s += 4) {
        int i0 = g_src[s], i1 = g_src[s + 1], i2 = g_src[s + 2], i3 = g_src[s + 3];
        float w0 = g_nrm[s], w1 = g_nrm[s + 1], w2 = g_nrm[s + 2], w3 = g_nrm[s + 3];
        uint4 r0 = ((const uint4*)(xw + (size_t)i0 * HD))[lane];
        uint4 r1 = ((const uint4*)(xw + (size_t)i1 * HD))[lane];
        uint4 r2 = ((const uint4*)(xw + (size_t)i2 * HD))[lane];
        uint4 r3 = ((const uint4*)(xw + (size_t)i3 * HD))[lane];
        accum(r0, w0); accum(r1, w1); accum(r2, w2); accum(r3, w3);
    }
    for (; s < s1; s++) {
        uint4 r0 = ((const uint4*)(xw + (size_t)g_src[s] * HD))[lane];
        accum(r0, g_nrm[s]);
    }

    const float4* bp = (const float4*)bias + (lane << 1);
    float4 b0 = bp[0], b1 = bp[1];
    a[0] += b0.x; a[1] += b0.y; a[2] += b0.z; a[3] += b0.w;
    a[4] += b1.x; a[5] += b1.y; a[6] += b1.z; a[7] += b1.w;

    float sm = 0.f, sq = 0.f;
#pragma unroll
    for (int i = 0; i < 8; i++) { sm += a[i]; sq += a[i] * a[i]; }
#pragma unroll
    for (int o = 16; o > 0; o >>= 1) {
        sm += __shfl_xor_sync(0xffffffffu, sm, o);
        sq += __shfl_xor_sync(0xffffffffu, sq, o);
    }
    float mu = sm * (1.f / HD);
    float inv = rsqrtf(sq * (1.f / HD) - mu * mu + EPSV);

    const float4* gp = (const float4*)gam + (lane << 1);
    const float4* ep = (const float4*)bet + (lane << 1);
    float4 gg0 = gp[0], gg1 = gp[1], ee0 = ep[0], ee1 = ep[1];
    float gv[8] = { gg0.x, gg0.y, gg0.z, gg0.w, gg1.x, gg1.y, gg1.z, gg1.w };
    float ev[8] = { ee0.x, ee0.y, ee0.z, ee0.w, ee1.x, ee1.y, ee1.z, ee1.w };
    float r[8];
#pragma unroll
    for (int i = 0; i < 8; i++)
        r[i] = fmaxf((a[i] - mu) * inv * gv[i] + ev[i], 0.f);

    size_t obase = (size_t)n * HD + lane * 8;
    if (MODE == 2 || MODE == 3) {
        union { uint4 u; __half h[8]; } pu;
        pu.u = *(const uint4*)(prev + obase);
#pragma unroll
        for (int i = 0; i < 8; i++) {
            float pv = __half2float(pu.h[i]);
            r[i] = (MODE == 2) ? (r[i] + 0.7f * pv) : (r[i] * 0.7f + pv);
        }
    }

    union { __half h[8]; uint4 u; } uo;
#pragma unroll
    for (int i = 0; i < 8; i++) uo.h[i] = __float2half_rn(r[i]);
    *(uint4*)(outp + obase) = uo.u;
}

// ==================== orchestration ====================
extern "C" void kernel_launch(void* const* d_in, const int* in_sizes, int n_in,
                              void* d_out, int out_size)
{
    const float* x   = (const float*)d_in[0];
    const void*  ei  = d_in[1];
    const float* W1  = (const float*)d_in[2];
    const float* b1  = (const float*)d_in[3];
    const float* g1  = (const float*)d_in[4];
    const float* be1 = (const float*)d_in[5];
    const float* W2  = (const float*)d_in[6];
    const float* b2  = (const float*)d_in[7];
    const float* g2  = (const float*)d_in[8];
    const float* be2 = (const float*)d_in[9];
    const float* W3  = (const float*)d_in[10];
    const float* b3  = (const float*)d_in[11];
    const float* g3  = (const float*)d_in[12];
    const float* be3 = (const float*)d_in[13];
    const float* Wf1 = (const float*)d_in[14];
    const float* bf1 = (const float*)d_in[15];
    const float* Wf2 = (const float*)d_in[16];
    const float* bf2 = (const float*)d_in[17];
    float* out = (float*)d_out;

    __half *xw_p, *af, *w1h, *w1l, *w2h, *w2l, *w3h, *w3l, *wf1h, *wf1l;
    cudaGetSymbolAddress((void**)&xw_p, g_xw);
    cudaGetSymbolAddress((void**)&af, g_af);
    cudaGetSymbolAddress((void**)&w1h, g_w1t_h);  cudaGetSymbolAddress((void**)&w1l, g_w1t_l);
    cudaGetSymbolAddress((void**)&w2h, g_w2t_h);  cudaGetSymbolAddress((void**)&w2l, g_w2t_l);
    cudaGetSymbolAddress((void**)&w3h, g_w3t_h);  cudaGetSymbolAddress((void**)&w3l, g_w3t_l);
    cudaGetSymbolAddress((void**)&wf1h, g_wf1t_h); cudaGetSymbolAddress((void**)&wf1l, g_wf1t_l);

    const int SMEM = 3 * 30720;
    cudaFuncSetAttribute(k_mma<128>, cudaFuncAttributeMaxDynamicSharedMemorySize, SMEM);
    cudaFuncSetAttribute(k_mma<256>, cudaFuncAttributeMaxDynamicSharedMemorySize, SMEM);
    cudaFuncSetAttribute(k_head,     cudaFuncAttributeMaxDynamicSharedMemorySize, SMEM);

    const int TB = 256;
    int gN = (NN + TB - 1) / TB;
    int gWarp = (NN * 32 + TB - 1) / TB;
    int mBlocks = (NN + 127) / 128;

    // #1 weight transpose+split, #2 x -> fp16, #3 detect+init
    k_wtall<<<(196608 + TB - 1) / TB, TB>>>(W1, W2, W3, Wf1,
        w1h, w1l, w2h, w2l, w3h, w3l, wf1h, wf1l);
    k_xcvt<<<(NN * 128 + TB - 1) / TB, TB>>>(x, af, NN * 128);
    k_detinit<<<gN, TB>>>((const int*)ei);

    // #4 layer-1 GEMM (ncu capture target)
    k_mma<128><<<dim3(2, mBlocks), 256, SMEM>>>(af, w1h, w1l, xw_p, NN, 256);

    // #5-#7 CSR build
    k_deg<<<(NE + TB - 1) / TB, TB>>>(ei);
    k_scan<<<1, 1024>>>();
    k_fillself<<<(NN + NE + TB - 1) / TB, TB>>>(ei);

    // #8 layer-1 aggregate (fp16 gather -> fp16 activations)
    k_agg<1><<<gWarp, TB>>>(xw_p, b1, g1, be1, nullptr, af);

    // #9-#10 layer 2
    k_mma<256><<<dim3(2, mBlocks), 256, SMEM>>>(af, w2h, w2l, xw_p, NN, 256);
    k_agg<2><<<gWarp, TB>>>(xw_p, b2, g2, be2, af, af);

    // #11-#12 layer 3
    k_mma<256><<<dim3(2, mBlocks), 256, SMEM>>>(af, w3h, w3l, xw_p, NN, 256);
    k_agg<3><<<gWarp, TB>>>(xw_p, b3, g3, be3, af, af);

    // #13 MLP head fused with final projection
    k_head<<<mBlocks, 256, SMEM>>>(af, wf1h, wf1l, bf1, NN, Wf2, bf2, out);
}

// round 10
// speedup vs baseline: 1.7506x; 1.1514x over previous
#include <cuda_runtime.h>
#include <cuda_fp16.h>
#include <cstdint>

#define NN 50000
#define NE 800000
#define NM (NE + NN)
#define HD 256
#define EPSV 1e-5f

// ==================== PTX helpers ====================
#define LDSM4(r, addr) asm volatile( \
    "ldmatrix.sync.aligned.m8n8.x4.shared.b16 {%0,%1,%2,%3}, [%4];" \
    : "=r"((r)[0]), "=r"((r)[1]), "=r"((r)[2]), "=r"((r)[3]) : "r"(addr))

#define MMA_FP16(d, a, b0, b1) asm volatile( \
    "mma.sync.aligned.m16n8k16.row.col.f32.f16.f16.f32 " \
    "{%0,%1,%2,%3}, {%4,%5,%6,%7}, {%8,%9}, {%0,%1,%2,%3};" \
    : "+f"((d)[0]), "+f"((d)[1]), "+f"((d)[2]), "+f"((d)[3]) \
    : "r"((a)[0]), "r"((a)[1]), "r"((a)[2]), "r"((a)[3]), "r"(b0), "r"(b1))

#define CP_ASYNC16(dst, src) \
    asm volatile("cp.async.cg.shared.global [%0], [%1], 16;" :: "r"(dst), "l"(src))
#define CP_COMMIT() asm volatile("cp.async.commit_group;" ::: "memory")
#define CP_WAIT1() asm volatile("cp.async.wait_group 1;" ::: "memory")
#define CP_WAIT0() asm volatile("cp.async.wait_group 0;" ::: "memory")

__device__ __forceinline__ uint32_t smem_to_u32(const void* smem_ptr) {
    uint32_t addr;
    asm("{ .reg .u64 tmp; cvta.to.shared.u64 tmp, %1; cvt.u32.u64 %0, tmp; }"
        : "=r"(addr) : "l"(smem_ptr));
    return addr;
}

// ==================== device scratch ====================
__device__ __align__(256) __half g_xw[(size_t)NN * HD];      // GEMM out, fp16
__device__ __align__(256) __half g_af[(size_t)NN * HD];      // activations, fp16
__device__ __align__(256) __half g_w1t[256 * 128];
__device__ __align__(256) __half g_w2t[256 * 256];
__device__ __align__(256) __half g_w3t[256 * 256];
__device__ __align__(256) __half g_wf1t[128 * 256];
__device__ int   g_cnt[NN];
__device__ int   g_off[NN + 1];
__device__ int   g_cur[NN];
__device__ int   g_src[NM];
__device__ float g_nrm[NM];
__device__ int   g_is64;

__device__ __forceinline__ int edge_val(const void* ei, int which, int e) {
    if (g_is64) return (int)((const long long*)ei)[(size_t)which * NE + e];
    return ((const int*)ei)[(size_t)which * NE + e];
}

// ======= fused: warp-parallel edge dtype detect + cnt/cur init =======
__global__ void k_detinit(const int* __restrict__ p) {
    int i = blockIdx.x * blockDim.x + threadIdx.x;
    if (blockIdx.x == 0 && threadIdx.x < 32) {
        int lane = threadIdx.x;
        int nz = 0;
        for (int j = lane; j < 1024; j += 32) nz |= p[2 * j + 1];
        unsigned any = __ballot_sync(0xffffffffu, nz != 0);
        if (lane == 0) g_is64 = (any == 0) ? 1 : 0;
    }
    if (i < NN) { g_cnt[i] = 1; g_cur[i] = 1; }
}

__global__ void k_deg(const void* __restrict__ ei) {
    int e = blockIdx.x * blockDim.x + threadIdx.x;
    if (e < NE) atomicAdd(&g_cnt[edge_val(ei, 1, e)], 1);
}

// single-block exclusive scan over g_cnt -> g_off
__global__ void k_scan() {
    __shared__ int s[1024];
    const int CH = (NN + 1023) / 1024;
    int tid = threadIdx.x;
    int base = tid * CH;
    int sum = 0;
    for (int i = 0; i < CH; i++) { int idx = base + i; if (idx < NN) sum += g_cnt[idx]; }
    s[tid] = sum;
    __syncthreads();
    for (int o = 1; o < 1024; o <<= 1) {
        int v = (tid >= o) ? s[tid - o] : 0;
        __syncthreads();
        s[tid] += v;
        __syncthreads();
    }
    int run = (tid == 0) ? 0 : s[tid - 1];
    for (int i = 0; i < CH; i++) {
        int idx = base + i;
        if (idx < NN) { g_off[idx] = run; run += g_cnt[idx]; }
    }
    if (tid == 1023) g_off[NN] = s[1023];
}

// ============ fused: self-loops + edge fill ============
__global__ void k_fillself(const void* __restrict__ ei) {
    int t = blockIdx.x * blockDim.x + threadIdx.x;
    if (t < NN) {
        int o = g_off[t];
        g_src[o] = t;
        g_nrm[o] = 1.0f / (float)g_cnt[t];
    } else if (t < NN + NE) {
        int e = t - NN;
        int r = edge_val(ei, 0, e);
        int c = edge_val(ei, 1, e);
        int p = atomicAdd(&g_cur[c], 1);
        int s = g_off[c] + p;
        g_src[s] = r;
        g_nrm[s] = rsqrtf((float)g_cnt[r]) * rsqrtf((float)g_cnt[c]);
    }
}

// ====== fused weight transpose + fp16 convert for all 4 weights ======
__global__ void k_wtall(
    const float* __restrict__ W1, const float* __restrict__ W2,
    const float* __restrict__ W3, const float* __restrict__ Wf1,
    __half* __restrict__ w1t, __half* __restrict__ w2t,
    __half* __restrict__ w3t, __half* __restrict__ wft)
{
    int idx = blockIdx.x * blockDim.x + threadIdx.x;
    const float* W; __half* T; int K, Nc, local;
    if (idx < 32768)       { W = W1;  T = w1t; K = 128; Nc = 256; local = idx; }
    else if (idx < 98304)  { W = W2;  T = w2t; K = 256; Nc = 256; local = idx - 32768; }
    else if (idx < 163840) { W = W3;  T = w3t; K = 256; Nc = 256; local = idx - 98304; }
    else if (idx < 196608) { W = Wf1; T = wft; K = 256; Nc = 128; local = idx - 163840; }
    else return;
    int k = local / Nc, n = local % Nc;
    T[(size_t)n * K + k] = __float2half_rn(W[local]);
}

// ==================== x -> fp16 single ====================
__global__ void k_xcvt(const float* __restrict__ x, __half* __restrict__ Af, int total) {
    int idx = blockIdx.x * blockDim.x + threadIdx.x;
    if (idx >= total) return;
    Af[idx] = __float2half_rn(x[idx]);
}

// ============== fp16 GEMM: 32x64 warp tile, 3-stage, 2 CTAs/SM ==========
// C[M,Nc](fp16) = A[M,K] @ W[K,Nc].  Both fp16 single.  Stage = 20KB.
template<int K>
__global__ __launch_bounds__(256, 2) void k_mma(
    const __half* __restrict__ Af, const __half* __restrict__ Bt,
    __half* __restrict__ C, int M, int Nc)
{
    constexpr int BK = 32;
    constexpr int NC_CHUNK = K / BK;
    constexpr int SA = BK + 8;
    constexpr int QTR = 128 * SA * 2;          // 10240 B
    constexpr int STAGE = 2 * QTR;             // 20480 B (A, B)

    extern __shared__ char smem[];
    uint32_t smem_base = smem_to_u32(smem);
    int tid = threadIdx.x;
    int lane = tid & 31;
    int wid = tid >> 5;
    int bm = blockIdx.y * 128;
    int bn = blockIdx.x * 128;
    int wm = (wid >> 1) * 32;
    int wn = (wid & 1) * 64;
    int lt = lane >> 3;
    int lr = lane & 7;

    uint32_t a_base[2];
#pragma unroll
    for (int mi = 0; mi < 2; mi++)
        a_base[mi] = smem_base +
            ((wm + mi * 16 + (lt & 1) * 8 + lr) * SA + (lt >> 1) * 8) * 2;
    uint32_t b_base[4];
#pragma unroll
    for (int nj = 0; nj < 4; nj++)
        b_base[nj] = smem_base + QTR +
            ((wn + nj * 16 + (lt >> 1) * 8 + lr) * SA + (lt & 1) * 8) * 2;

    auto issue_chunk = [&](int c) {
        uint32_t dst = smem_base + (uint32_t)(c % 3) * STAGE;
#pragma unroll
        for (int t = 0; t < 4; t++) {
            int i = tid + t * 256;              // 0..1023
            if (i < 512) {                      // A
                int m = i >> 2, k = (i & 3) * 8;
                int gm = bm + m;
                if (gm > M - 1) gm = M - 1;
                CP_ASYNC16(dst + (m * SA + k) * 2,
                           Af + (size_t)gm * K + c * BK + k);
            } else {                            // B
                int j = i - 512;
                int n = j >> 2, k = (j & 3) * 8;
                CP_ASYNC16(dst + QTR + (n * SA + k) * 2,
                           Bt + (size_t)(bn + n) * K + c * BK + k);
            }
        }
    };

    float acc[2][8][4];
#pragma unroll
    for (int mi = 0; mi < 2; mi++)
#pragma unroll
        for (int ni = 0; ni < 8; ni++)
#pragma unroll
            for (int v = 0; v < 4; v++) acc[mi][ni][v] = 0.f;

    issue_chunk(0); CP_COMMIT();
    if (NC_CHUNK > 1) { issue_chunk(1); CP_COMMIT(); }

    for (int c = 0; c < NC_CHUNK; c++) {
        if (c + 1 < NC_CHUNK) CP_WAIT1(); else CP_WAIT0();
        __syncthreads();
        if (c + 2 < NC_CHUNK) { issue_chunk(c + 2); CP_COMMIT(); }

        uint32_t sbuf = (uint32_t)(c % 3) * STAGE;
#pragma unroll
        for (int ks = 0; ks < BK / 16; ks++) {
            uint32_t o = sbuf + ks * 32;
            uint32_t af[2][4];
            LDSM4(af[0], a_base[0] + o);
            LDSM4(af[1], a_base[1] + o);
            uint32_t bB[2][4];
            LDSM4(bB[0], b_base[0] + o);
#pragma unroll
            for (int nj = 0; nj < 4; nj++) {
                int cur = nj & 1, nxt = cur ^ 1;
                if (nj < 3) LDSM4(bB[nxt], b_base[nj + 1] + o);
                MMA_FP16(acc[0][2 * nj],     af[0], bB[cur][0], bB[cur][1]);
                MMA_FP16(acc[1][2 * nj],     af[1], bB[cur][0], bB[cur][1]);
                MMA_FP16(acc[0][2 * nj + 1], af[0], bB[cur][2], bB[cur][3]);
                MMA_FP16(acc[1][2 * nj + 1], af[1], bB[cur][2], bB[cur][3]);
            }
        }
    }

    // ---- epilogue: fp16 stores ----
    int g = lane >> 2, tg = lane & 3;
#pragma unroll
    for (int mi = 0; mi < 2; mi++) {
        int r0 = bm + wm + mi * 16 + g;
#pragma unroll
        for (int ni = 0; ni < 8; ni++) {
            int col = bn + wn + ni * 8 + tg * 2;
            __half2 v0 = __floats2half2_rn(acc[mi][ni][0], acc[mi][ni][1]);
            __half2 v1 = __floats2half2_rn(acc[mi][ni][2], acc[mi][ni][3]);
            if (r0 < M)     *(__half2*)(C + (size_t)r0 * Nc + col) = v0;
            if (r0 + 8 < M) *(__half2*)(C + (size_t)(r0 + 8) * Nc + col) = v1;
        }
    }
}

// ======== head GEMM with fused relu + Wf2 reduction (fp16 single) ========
__global__ __launch_bounds__(256, 2) void k_head(
    const __half* __restrict__ Af, const __half* __restrict__ Bt,
    const float* __restrict__ bias, int M,
    const float* __restrict__ wf2, const float* __restrict__ bf2,
    float* __restrict__ outp)
{
    constexpr int K = 256;
    constexpr int BK = 32;
    constexpr int NC_CHUNK = K / BK;
    constexpr int SA = BK + 8;
    constexpr int QTR = 128 * SA * 2;
    constexpr int STAGE = 2 * QTR;

    extern __shared__ char smem[];
    __shared__ float red[128];
    uint32_t smem_base = smem_to_u32(smem);
    int tid = threadIdx.x;
    int lane = tid & 31;
    int wid = tid >> 5;
    int bm = blockIdx.x * 128;
    int wm = (wid >> 1) * 32;
    int wn = (wid & 1) * 64;
    int lt = lane >> 3;
    int lr = lane & 7;

    if (tid < 128) red[tid] = 0.f;

    uint32_t a_base[2];
#pragma unroll
    for (int mi = 0; mi < 2; mi++)
        a_base[mi] = smem_base +
            ((wm + mi * 16 + (lt & 1) * 8 + lr) * SA + (lt >> 1) * 8) * 2;
    uint32_t b_base[4];
#pragma unroll
    for (int nj = 0; nj < 4; nj++)
        b_base[nj] = smem_base + QTR +
            ((wn + nj * 16 + (lt >> 1) * 8 + lr) * SA + (lt & 1) * 8) * 2;

    auto issue_chunk = [&](int c) {
        uint32_t dst = smem_base + (uint32_t)(c % 3) * STAGE;
#pragma unroll
        for (int t = 0; t < 4; t++) {
            int i = tid + t * 256;
            if (i < 512) {
                int m = i >> 2, k = (i & 3) * 8;
                int gm = bm + m;
                if (gm > M - 1) gm = M - 1;
                CP_ASYNC16(dst + (m * SA + k) * 2,
                           Af + (size_t)gm * K + c * BK + k);
            } else {
                int j = i - 512;
                int n = j >> 2, k = (j & 3) * 8;
                CP_ASYNC16(dst + QTR + (n * SA + k) * 2,
                           Bt + (size_t)n * K + c * BK + k);   // Nc=128, bn=0
            }
        }
    };

    float acc[2][8][4];
#pragma unroll
    for (int mi = 0; mi < 2; mi++)
#pragma unroll
        for (int ni = 0; ni < 8; ni++)
#pragma unroll
            for (int v = 0; v < 4; v++) acc[mi][ni][v] = 0.f;

    issue_chunk(0); CP_COMMIT();
    issue_chunk(1); CP_COMMIT();

    for (int c = 0; c < NC_CHUNK; c++) {
        if (c + 1 < NC_CHUNK) CP_WAIT1(); else CP_WAIT0();
        __syncthreads();
        if (c + 2 < NC_CHUNK) { issue_chunk(c + 2); CP_COMMIT(); }

        uint32_t sbuf = (uint32_t)(c % 3) * STAGE;
#pragma unroll
        for (int ks = 0; ks < BK / 16; ks++) {
            uint32_t o = sbuf + ks * 32;
            uint32_t af[2][4];
            LDSM4(af[0], a_base[0] + o);
            LDSM4(af[1], a_base[1] + o);
            uint32_t bB[2][4];
            LDSM4(bB[0], b_base[0] + o);
#pragma unroll
            for (int nj = 0; nj < 4; nj++) {
                int cur = nj & 1, nxt = cur ^ 1;
                if (nj < 3) LDSM4(bB[nxt], b_base[nj + 1] + o);
                MMA_FP16(acc[0][2 * nj],     af[0], bB[cur][0], bB[cur][1]);
                MMA_FP16(acc[1][2 * nj],     af[1], bB[cur][0], bB[cur][1]);
                MMA_FP16(acc[0][2 * nj + 1], af[0], bB[cur][2], bB[cur][3]);
                MMA_FP16(acc[1][2 * nj + 1], af[1], bB[cur][2], bB[cur][3]);
            }
        }
    }

    int g = lane >> 2, tg = lane & 3;
    __syncthreads();
#pragma unroll
    for (int mi = 0; mi < 2; mi++) {
        float p0 = 0.f, p1 = 0.f;
#pragma unroll
        for (int ni = 0; ni < 8; ni++) {
            int col = wn + ni * 8 + tg * 2;
            float bx = bias[col], by = bias[col + 1];
            float w0 = wf2[col], w1 = wf2[col + 1];
            p0 += fmaxf(acc[mi][ni][0] + bx, 0.f) * w0
                + fmaxf(acc[mi][ni][1] + by, 0.f) * w1;
            p1 += fmaxf(acc[mi][ni][2] + bx, 0.f) * w0
                + fmaxf(acc[mi][ni][3] + by, 0.f) * w1;
        }
        atomicAdd(&red[wm + mi * 16 + g], p0);
        atomicAdd(&red[wm + mi * 16 + 8 + g], p1);
    }
    __syncthreads();
    if (tid < 128) {
        int r = bm + tid;
        if (r < M) outp[r] = red[tid] + bf2[0];
    }
}

// ======== fused aggregate(+bias)+LN+ReLU+residual, fp16 gather ========
template<int MODE>
__global__ __launch_bounds__(256) void k_agg(
    const __half* __restrict__ xw, const float* __restrict__ bias,
    const float* __restrict__ gam, const float* __restrict__ bet,
    const __half* __restrict__ prev, __half* __restrict__ outp)
{
    int n = (blockIdx.x * blockDim.x + threadIdx.x) >> 5;
    int lane = threadIdx.x & 31;
    if (n >= NN) return;
    int s0 = g_off[n], s1 = g_off[n + 1];
    float a[8] = {0.f, 0.f, 0.f, 0.f, 0.f, 0.f, 0.f, 0.f};
    int s = s0;

    auto accum = [&](uint4 raw, float w) {
        union { uint4 u; __half2 h[4]; } cv;
        cv.u = raw;
#pragma unroll
        for (int q = 0; q < 4; q++) {
            float2 f = __half22float2(cv.h[q]);
            a[2 * q]     += w * f.x;
            a[2 * q + 1] += w * f.y;
        }
    };

    for (; s + 3 < s1; s += 4) {
        int i0 = g_src[s], i1 = g_src[s + 1], i2 = g_src[s + 2], i3 = g_src[s + 3];
        float w0 = g_nrm[s], w1 = g_nrm[s + 1], w2 = g_nrm[s + 2], w3 = g_nrm[s + 3];
        uint4 r0 = ((const uint4*)(xw + (size_t)i0 * HD))[lane];
        uint4 r1 = ((const uint4*)(xw + (size_t)i1 * HD))[lane];
        uint4 r2 = ((const uint4*)(xw + (size_t)i2 * HD))[lane];
        uint4 r3 = ((const uint4*)(xw + (size_t)i3 * HD))[lane];
        accum(r0, w0); accum(r1, w1); accum(r2, w2); accum(r3, w3);
    }
    for (; s < s1; s++) {
        uint4 r0 = ((const uint4*)(xw + (size_t)g_src[s] * HD))[lane];
        accum(r0, g_nrm[s]);
    }

    const float4* bp = (const float4*)bias + (lane << 1);
    float4 b0 = bp[0], b1 = bp[1];
    a[0] += b0.x; a[1] += b0.y; a[2] += b0.z; a[3] += b0.w;
    a[4] += b1.x; a[5] += b1.y; a[6] += b1.z; a[7] += b1.w;

    float sm = 0.f, sq = 0.f;
#pragma unroll
    for (int i = 0; i < 8; i++) { sm += a[i]; sq += a[i] * a[i]; }
#pragma unroll
    for (int o = 16; o > 0; o >>= 1) {
        sm += __shfl_xor_sync(0xffffffffu, sm, o);
        sq += __shfl_xor_sync(0xffffffffu, sq, o);
    }
    float mu = sm * (1.f / HD);
    float inv = rsqrtf(sq * (1.f / HD) - mu * mu + EPSV);

    const float4* gp = (const float4*)gam + (lane << 1);
    const float4* ep = (const float4*)bet + (lane << 1);
    float4 gg0 = gp[0], gg1 = gp[1], ee0 = ep[0], ee1 = ep[1];
    float gv[8] = { gg0.x, gg0.y, gg0.z, gg0.w, gg1.x, gg1.y, gg1.z, gg1.w };
    float ev[8] = { ee0.x, ee0.y, ee0.z, ee0.w, ee1.x, ee1.y, ee1.z, ee1.w };
    float r[8];
#pragma unroll
    for (int i = 0; i < 8; i++)
        r[i] = fmaxf((a[i] - mu) * inv * gv[i] + ev[i], 0.f);

    size_t obase = (size_t)n * HD + lane * 8;
    if (MODE == 2 || MODE == 3) {
        union { uint4 u; __half h[8]; } pu;
        pu.u = *(const uint4*)(prev + obase);
#pragma unroll
        for (int i = 0; i < 8; i++) {
            float pv = __half2float(pu.h[i]);
            r[i] = (MODE == 2) ? (r[i] + 0.7f * pv) : (r[i] * 0.7f + pv);
        }
    }

    union { __half h[8]; uint4 u; } uo;
#pragma unroll
    for (int i = 0; i < 8; i++) uo.h[i] = __float2half_rn(r[i]);
    *(uint4*)(outp + obase) = uo.u;
}

// ==================== orchestration ====================
extern "C" void kernel_launch(void* const* d_in, const int* in_sizes, int n_in,
                              void* d_out, int out_size)
{
    const float* x   = (const float*)d_in[0];
    const void*  ei  = d_in[1];
    const float* W1  = (const float*)d_in[2];
    const float* b1  = (const float*)d_in[3];
    const float* g1  = (const float*)d_in[4];
    const float* be1 = (const float*)d_in[5];
    const float* W2  = (const float*)d_in[6];
    const float* b2  = (const float*)d_in[7];
    const float* g2  = (const float*)d_in[8];
    const float* be2 = (const float*)d_in[9];
    const float* W3  = (const float*)d_in[10];
    const float* b3  = (const float*)d_in[11];
    const float* g3  = (const float*)d_in[12];
    const float* be3 = (const float*)d_in[13];
    const float* Wf1 = (const float*)d_in[14];
    const float* bf1 = (const float*)d_in[15];
    const float* Wf2 = (const float*)d_in[16];
    const float* bf2 = (const float*)d_in[17];
    float* out = (float*)d_out;

    __half *xw_p, *af, *w1t, *w2t, *w3t, *wft;
    cudaGetSymbolAddress((void**)&xw_p, g_xw);
    cudaGetSymbolAddress((void**)&af, g_af);
    cudaGetSymbolAddress((void**)&w1t, g_w1t);
    cudaGetSymbolAddress((void**)&w2t, g_w2t);
    cudaGetSymbolAddress((void**)&w3t, g_w3t);
    cudaGetSymbolAddress((void**)&wft, g_wf1t);

    const int SMEM = 3 * 20480;   // 3 stages x 20KB = 61440 B
    cudaFuncSetAttribute(k_mma<128>, cudaFuncAttributeMaxDynamicSharedMemorySize, SMEM);
    cudaFuncSetAttribute(k_mma<256>, cudaFuncAttributeMaxDynamicSharedMemorySize, SMEM);
    cudaFuncSetAttribute(k_head,     cudaFuncAttributeMaxDynamicSharedMemorySize, SMEM);

    const int TB = 256;
    int gN = (NN + TB - 1) / TB;
    int gWarp = (NN * 32 + TB - 1) / TB;
    int mBlocks = (NN + 127) / 128;

    // #1 weight transpose+fp16, #2 x -> fp16, #3 detect+init
    k_wtall<<<(196608 + TB - 1) / TB, TB>>>(W1, W2, W3, Wf1, w1t, w2t, w3t, wft);
    k_xcvt<<<(NN * 128 + TB - 1) / TB, TB>>>(x, af, NN * 128);
    k_detinit<<<gN, TB>>>((const int*)ei);

    // #4 layer-1 GEMM (ncu capture target)
    k_mma<128><<<dim3(2, mBlocks), 256, SMEM>>>(af, w1t, xw_p, NN, 256);

    // #5-#7 CSR build
    k_deg<<<(NE + TB - 1) / TB, TB>>>(ei);
    k_scan<<<1, 1024>>>();
    k_fillself<<<(NN + NE + TB - 1) / TB, TB>>>(ei);

    // #8 layer-1 aggregate
    k_agg<1><<<gWarp, TB>>>(xw_p, b1, g1, be1, nullptr, af);

    // #9-#10 layer 2
    k_mma<256><<<dim3(2, mBlocks), 256, SMEM>>>(af, w2t, xw_p, NN, 256);
    k_agg<2><<<gWarp, TB>>>(xw_p, b2, g2, be2, af, af);

    // #11-#12 layer 3
    k_mma<256><<<dim3(2, mBlocks), 256, SMEM>>>(af, w3t, xw_p, NN, 256);
    k_agg<3><<<gWarp, TB>>>(xw_p, b3, g3, be3, af, af);

    // #13 MLP head fused with final projection
    k_head<<<mBlocks, 256, SMEM>>>(af, wft, bf1, NN, Wf2, bf2, out);
}